// round 14
// baseline (speedup 1.0000x reference)
#include <cuda_runtime.h>
#include <cuda_bf16.h>
#include <cstdint>

// ---------------- problem constants ----------------
#define B       2
#define T       32768
#define BT      (B*T)           // 65536
#define R2      16384
#define POOL_N  (3*B*R2*128)
#define CNT_N   (3*B*R2)

// ---------------- scratch ----------------
__device__ float    g_net[BT*128];
__device__ uint32_t g_poolA[POOL_N];   // tagged-max pools (ping-pong)
__device__ uint32_t g_poolB[POOL_N];
__device__ float    g_mean[POOL_N];    // scatter-mean accumulator
__device__ float    g_cnt[CNT_N];
__device__ int      g_idx[3][BT];
__device__ __nv_bfloat16 g_wt[851968];

// ---------------- helpers ----------------
__device__ __forceinline__ uint32_t smem_u32(const void* p) {
    uint32_t a;
    asm("{ .reg .u64 t; cvta.to.shared.u64 t, %1; cvt.u32.u64 %0, t; }" : "=r"(a) : "l"(p));
    return a;
}
__device__ __forceinline__ void ldsm4(uint32_t& r0, uint32_t& r1, uint32_t& r2, uint32_t& r3,
                                      uint32_t a) {
    asm volatile("ldmatrix.sync.aligned.m8n8.x4.shared.b16 {%0,%1,%2,%3}, [%4];"
        : "=r"(r0), "=r"(r1), "=r"(r2), "=r"(r3) : "r"(a));
}
__device__ __forceinline__ void mma16816(float* c, const uint32_t* a, uint32_t b0, uint32_t b1) {
    asm volatile("mma.sync.aligned.m16n8k16.row.col.f32.bf16.bf16.f32 "
        "{%0,%1,%2,%3}, {%4,%5,%6,%7}, {%8,%9}, {%0,%1,%2,%3};"
        : "+f"(c[0]), "+f"(c[1]), "+f"(c[2]), "+f"(c[3])
        : "r"(a[0]), "r"(a[1]), "r"(a[2]), "r"(a[3]), "r"(b0), "r"(b1));
}
__device__ __forceinline__ uint32_t b2u(__nv_bfloat162 v) {
    return *reinterpret_cast<uint32_t*>(&v);
}
__device__ __forceinline__ void cp16(uint32_t dst, const void* src) {
    asm volatile("cp.async.ca.shared.global [%0], [%1], 16;" :: "r"(dst), "l"(src));
}
// 128B-row swizzle
__device__ __forceinline__ uint32_t sw(int r, int cb) {
    return (uint32_t)(r * 128 + ((((cb >> 4) ^ (r & 7)) & 7) << 4) + (cb & 15));
}
// ---- tagged-max encoding: [31:29]=tag, [28:0]=order-preserving float enc >> 3
__device__ __forceinline__ uint32_t penc(float f, uint32_t tag) {
    uint32_t u = __float_as_uint(f);
    uint32_t e = (u >> 31) ? ~u : (u | 0x80000000u);
    return (tag << 29) | (e >> 3);
}
__device__ __forceinline__ float pdec(uint32_t w) {
    uint32_t e = (w & 0x1FFFFFFFu) << 3;
    return (e & 0x80000000u) ? __uint_as_float(e & 0x7FFFFFFFu)
                             : __uint_as_float(~e);
}

// ---------------- single upfront reset (pools + mean + cnt) ----------------
__global__ void k_reset() {
    int i = blockIdx.x * blockDim.x + threadIdx.x;
    const int Q = POOL_N / 4;
    uint4 z; z.x = z.y = z.z = z.w = 0u;
    if (i < Q)               ((uint4*)g_poolA)[i]      = z;
    else if (i < 2*Q)        ((uint4*)g_poolB)[i - Q]  = z;
    else if (i < 3*Q)        ((uint4*)g_mean)[i - 2*Q] = z;
    if (i < CNT_N) g_cnt[i] = 0.0f;
}

// ---------------- index computation ----------------
__global__ void k_index(const float* __restrict__ p) {
    int t = blockIdx.x * blockDim.x + threadIdx.x;
    if (t >= BT) return;
    float x = p[t*3+0], y = p[t*3+1], z = p[t*3+2];
    float cu[3] = {x, x, y};
    float cv[3] = {z, y, z};
    const float hi = (float)(1.0 - 1e-5);
    #pragma unroll
    for (int k = 0; k < 3; k++) {
        float u = cu[k] / 1.101f + 0.5f;
        float v = cv[k] / 1.101f + 0.5f;
        u = fminf(fmaxf(u, 0.0f), hi);
        v = fminf(fmaxf(v, 0.0f), hi);
        g_idx[k][t] = (int)(u * 128.0f) + 128 * (int)(v * 128.0f);
    }
}

// ---------------- weight pre-split ----------------
__global__ void k_wsplit(const float* __restrict__ W0, const float* __restrict__ W1,
                         const float* __restrict__ Ws, const float* __restrict__ fcW) {
    int i = blockIdx.x * blockDim.x + threadIdx.x;
    if (i >= 425984) return;
    const float* src; int K, base, e;
    if (i < 163840)       { int blk = i / 32768;            e = i % 32768; K = 256; src = W0 + blk*32768; base = blk*65536; }
    else if (i < 245760)  { int j = i - 163840; int blk = j / 16384; e = j % 16384; K = 128; src = W1 + blk*16384; base = 327680 + blk*32768; }
    else if (i < 409600)  { int j = i - 245760; int blk = j / 32768; e = j % 32768; K = 256; src = Ws + blk*32768; base = 491520 + blk*65536; }
    else                  { e = i - 409600; K = 128; src = fcW; base = 819200; }
    int n = e / K, k = e % K;
    float v = src[(size_t)k * 128 + n];
    __nv_bfloat16 hi = __float2bfloat16(v);
    __nv_bfloat16 lo = __float2bfloat16(v - __bfloat162float(hi));
    g_wt[base + (size_t)n * K + k]           = hi;
    g_wt[base + (size_t)128 * K + n * K + k] = lo;
}

// =====================================================================
// Fused ResNet-block kernel, 512 threads (16 warps, 4x4 grid, m32n32)
// =====================================================================
#define PLANE   16384
#define SETSZ   (4*PLANE)
#define SOFF    1024u
#define HIDOFF  (SOFF + 2*SETSZ)
#define FSMEM   (HIDOFF + 4*PLANE)               // 197632
#define NT      512

// term-major MMA issue: all 8 independent accs per term -> reuse distance 8
#define MMA_TERMS(acc, ah0, ah1, al0, al1, bh, bl)            \
    do {                                                      \
        _Pragma("unroll")                                     \
        for (int nf = 0; nf < 4; nf++) {                      \
            mma16816(acc[0][nf], ah0, bh[nf][0], bh[nf][1]);  \
            mma16816(acc[1][nf], ah1, bh[nf][0], bh[nf][1]);  \
        }                                                     \
        _Pragma("unroll")                                     \
        for (int nf = 0; nf < 4; nf++) {                      \
            mma16816(acc[0][nf], ah0, bl[nf][0], bl[nf][1]);  \
            mma16816(acc[1][nf], ah1, bl[nf][0], bl[nf][1]);  \
        }                                                     \
        _Pragma("unroll")                                     \
        for (int nf = 0; nf < 4; nf++) {                      \
            mma16816(acc[0][nf], al0, bh[nf][0], bh[nf][1]);  \
            mma16816(acc[1][nf], al1, bh[nf][0], bh[nf][1]);  \
        }                                                     \
    } while (0)

template<int ASRC, bool SCATTER>
__global__ __launch_bounds__(NT, 1)
void k_block(const float* __restrict__ A1,
             const float* __restrict__ P,
             const float* __restrict__ fcW,
             const float* __restrict__ fcb,
             const uint32_t* __restrict__ poolIn,
             uint32_t* __restrict__ poolOut,
             uint32_t tag,
             const __nv_bfloat16* __restrict__ W0hi, const __nv_bfloat16* __restrict__ W0lo,
             const __nv_bfloat16* __restrict__ W1hi, const __nv_bfloat16* __restrict__ W1lo,
             const __nv_bfloat16* __restrict__ WShi, const __nv_bfloat16* __restrict__ WSlo,
             const float* __restrict__ b0, const float* __restrict__ b1,
             float* __restrict__ C) {
    extern __shared__ __align__(16) char smem[];
    float* b0S = (float*)smem;
    float* b1S = (float*)(smem + 512);
    const int tid  = threadIdx.x, lane = tid & 31, wid = tid >> 5;
    const int m0   = blockIdx.x * 128;
    const int wm   = (wid & 3) * 32;
    const int wn   = (wid >> 2) * 32;
    const uint32_t sb = smem_u32(smem);

    if (tid < 128) { b0S[tid] = b0[tid]; b1S[tid] = b1[tid]; }

    const int aRow  = wm + (lane & 15);
    const int aCoff = (lane >> 4) * 8;
    const int bRow  = wn + (lane & 7) + ((lane >> 4) << 3);
    const int bCoff = ((lane >> 3) & 1) * 8;

    float acc[2][4][4] = {};

    auto loadA = [&](int ch, float4* vb) {
        const int K0 = ch * 64;
        #pragma unroll
        for (int j = 0; j < 4; j++) {
            int i = tid + j * NT;
            int r = i >> 4, c4 = (i & 15) << 2;
            int m = m0 + r;
            if (ASRC == 1) {
                float p0 = P[m*3+0], p1 = P[m*3+1], p2 = P[m*3+2];
                int cg = K0 + c4;
                float4 v;
                v.x = fmaf(p0, fcW[cg+0], fmaf(p1, fcW[256+cg+0], fmaf(p2, fcW[512+cg+0], fcb[cg+0])));
                v.y = fmaf(p0, fcW[cg+1], fmaf(p1, fcW[256+cg+1], fmaf(p2, fcW[512+cg+1], fcb[cg+1])));
                v.z = fmaf(p0, fcW[cg+2], fmaf(p1, fcW[256+cg+2], fmaf(p2, fcW[512+cg+2], fcb[cg+2])));
                v.w = fmaf(p0, fcW[cg+3], fmaf(p1, fcW[256+cg+3], fmaf(p2, fcW[512+cg+3], fcb[cg+3])));
                vb[j] = v;
            } else if (K0 >= 128) {
                int b = m >> 15;
                int c0 = (K0 - 128) + c4;
                float4 s; s.x = s.y = s.z = s.w = 0.0f;
                #pragma unroll
                for (int k = 0; k < 3; k++) {
                    int cell = g_idx[k][m];
                    uint4 pv = *(const uint4*)&poolIn[((size_t)((k*B + b)*R2) + cell)*128 + c0];
                    s.x += pdec(pv.x); s.y += pdec(pv.y);
                    s.z += pdec(pv.z); s.w += pdec(pv.w);
                }
                vb[j] = s;
            } else {
                vb[j] = *(const float4*)&A1[(size_t)m * 128 + K0 + c4];
            }
        }
    };
    auto storeA = [&](int set, const float4* vb, bool relu) {
        const uint32_t base = SOFF + (uint32_t)set * SETSZ;
        #pragma unroll
        for (int j = 0; j < 4; j++) {
            int i = tid + j * NT;
            int r = i >> 4, c4 = (i & 15) << 2;
            float4 v = vb[j];
            if (relu) {
                v.x = fmaxf(v.x, 0.f); v.y = fmaxf(v.y, 0.f);
                v.z = fmaxf(v.z, 0.f); v.w = fmaxf(v.w, 0.f);
            }
            __nv_bfloat162 h01, h23, l01, l23;
            h01.x = __float2bfloat16(v.x); h01.y = __float2bfloat16(v.y);
            h23.x = __float2bfloat16(v.z); h23.y = __float2bfloat16(v.w);
            l01.x = __float2bfloat16(v.x - __bfloat162float(h01.x));
            l01.y = __float2bfloat16(v.y - __bfloat162float(h01.y));
            l23.x = __float2bfloat16(v.z - __bfloat162float(h23.x));
            l23.y = __float2bfloat16(v.w - __bfloat162float(h23.y));
            uint32_t off = sw(r, c4 * 2);
            *(uint2*)(smem + base + off)         = make_uint2(b2u(h01), b2u(h23));
            *(uint2*)(smem + base + PLANE + off) = make_uint2(b2u(l01), b2u(l23));
        }
    };
    auto cpB = [&](const __nv_bfloat16* Whi, const __nv_bfloat16* Wlo, int K, int ch, int set) {
        const int K0 = ch * 64;
        const uint32_t base = sb + SOFF + (uint32_t)set * SETSZ + 2 * PLANE;
        #pragma unroll
        for (int j = 0; j < 2; j++) {
            int i = tid + j * NT;
            int r = i >> 3, c8 = (i & 7) << 3;
            uint32_t off = sw(r, c8 * 2);
            cp16(base + off,         &Whi[(size_t)r * K + K0 + c8]);
            cp16(base + PLANE + off, &Wlo[(size_t)r * K + K0 + c8]);
        }
        asm volatile("cp.async.commit_group;" ::: "memory");
    };
    auto mmaChunk = [&](uint32_t aBase, uint32_t bBase) {
        #pragma unroll
        for (int ks = 0; ks < 64; ks += 16) {
            uint32_t ah0[4], ah1[4], al0[4], al1[4];
            {
                uint32_t c0 = (uint32_t)((ks + aCoff) * 2);
                ldsm4(ah0[0], ah0[1], ah0[2], ah0[3], sb + aBase + sw(aRow,      c0));
                ldsm4(ah1[0], ah1[1], ah1[2], ah1[3], sb + aBase + sw(aRow + 16, c0));
                ldsm4(al0[0], al0[1], al0[2], al0[3], sb + aBase + PLANE + sw(aRow,      c0));
                ldsm4(al1[0], al1[1], al1[2], al1[3], sb + aBase + PLANE + sw(aRow + 16, c0));
            }
            uint32_t bh[4][2], bl[4][2];
            #pragma unroll
            for (int nf2 = 0; nf2 < 2; nf2++) {
                uint32_t ad = sw(bRow + nf2*16, (uint32_t)((ks + bCoff) * 2));
                ldsm4(bh[nf2*2][0], bh[nf2*2][1], bh[nf2*2+1][0], bh[nf2*2+1][1], sb + bBase + ad);
                ldsm4(bl[nf2*2][0], bl[nf2*2][1], bl[nf2*2+1][0], bl[nf2*2+1][1], sb + bBase + PLANE + ad);
            }
            MMA_TERMS(acc, ah0, ah1, al0, al1, bh, bl);
        }
    };

    // ================= phase W0 (K=256, relu A) =================
    float4 areg[4];
    loadA(0, areg);
    cpB(W0hi, W0lo, 256, 0, 0);
    #pragma unroll
    for (int ch = 0; ch < 4; ch++) {
        const int set = ch & 1;
        storeA(set, areg, true);
        asm volatile("cp.async.wait_group 0;" ::: "memory");
        __syncthreads();
        if (ch < 3) {
            cpB(W0hi, W0lo, 256, ch + 1, set ^ 1);
            loadA(ch + 1, areg);
        } else {
            cpB(W1hi, W1lo, 128, 0, 0);
        }
        mmaChunk(SOFF + (uint32_t)set * SETSZ, SOFF + (uint32_t)set * SETSZ + 2*PLANE);
    }
    __syncthreads();
    cpB(W1hi, W1lo, 128, 1, 1);
    loadA(0, areg);

    // hidden = relu(acc + b0) -> hidden planes; acc = b1
    #pragma unroll
    for (int mf = 0; mf < 2; mf++) {
        int mloc = wm + mf*16 + (lane >> 2);
        #pragma unroll
        for (int nf = 0; nf < 4; nf++) {
            int n = wn + nf*8 + (lane & 3) * 2;
            uint32_t hb = HIDOFF + (uint32_t)(n >> 6) * 2 * PLANE;
            #pragma unroll
            for (int q = 0; q < 2; q++) {
                int r = mloc + q * 8;
                float h0 = fmaxf(acc[mf][nf][2*q]   + b0S[n],   0.0f);
                float h1 = fmaxf(acc[mf][nf][2*q+1] + b0S[n+1], 0.0f);
                __nv_bfloat162 hh, ll;
                hh.x = __float2bfloat16(h0); hh.y = __float2bfloat16(h1);
                ll.x = __float2bfloat16(h0 - __bfloat162float(hh.x));
                ll.y = __float2bfloat16(h1 - __bfloat162float(hh.y));
                uint32_t off = sw(r, (n & 63) * 2);
                *(uint32_t*)(smem + hb + off)         = b2u(hh);
                *(uint32_t*)(smem + hb + PLANE + off) = b2u(ll);
            }
            #pragma unroll
            for (int q = 0; q < 4; q++) acc[mf][nf][q] = b1S[n + (q & 1)];
        }
    }
    asm volatile("cp.async.wait_group 0;" ::: "memory");
    __syncthreads();

    // ================= phase W1 (K=128, A = hidden planes) =================
    mmaChunk(HIDOFF,           SOFF + 2*PLANE);
    mmaChunk(HIDOFF + 2*PLANE, SOFF + SETSZ + 2*PLANE);
    __syncthreads();

    // ================= phase Ws (K=256, raw A), acc carries dx+b1 =================
    cpB(WShi, WSlo, 256, 0, 0);
    #pragma unroll
    for (int ch = 0; ch < 4; ch++) {
        const int set = ch & 1;
        storeA(set, areg, false);
        asm volatile("cp.async.wait_group 0;" ::: "memory");
        __syncthreads();
        if (ch < 3) {
            cpB(WShi, WSlo, 256, ch + 1, set ^ 1);
            loadA(ch + 1, areg);
        }
        mmaChunk(SOFF + (uint32_t)set * SETSZ, SOFF + (uint32_t)set * SETSZ + 2*PLANE);
    }

    // ---- epilogue: write net (+ tagged scatter-max)
    #pragma unroll
    for (int mf = 0; mf < 2; mf++) {
        const int m  = m0 + wm + mf*16 + (lane >> 2);
        const int bb = m >> 15;
        int cellA[3], cellB[3];
        if (SCATTER) {
            #pragma unroll
            for (int k = 0; k < 3; k++) {
                cellA[k] = g_idx[k][m];
                cellB[k] = g_idx[k][m + 8];
            }
        }
        #pragma unroll
        for (int nf = 0; nf < 4; nf++) {
            int n = wn + nf*8 + (lane & 3) * 2;
            float2 v0, v1;
            v0.x = acc[mf][nf][0]; v0.y = acc[mf][nf][1];
            v1.x = acc[mf][nf][2]; v1.y = acc[mf][nf][3];
            *(float2*)&C[(size_t)m * 128 + n]     = v0;
            *(float2*)&C[(size_t)(m+8) * 128 + n] = v1;
            if (SCATTER) {
                uint32_t e00 = penc(v0.x, tag), e01 = penc(v0.y, tag);
                uint32_t e10 = penc(v1.x, tag), e11 = penc(v1.y, tag);
                #pragma unroll
                for (int k = 0; k < 3; k++) {
                    uint32_t* pA = &poolOut[((size_t)((k*B + bb)*R2) + cellA[k])*128 + n];
                    uint32_t* pB = &poolOut[((size_t)((k*B + bb)*R2) + cellB[k])*128 + n];
                    atomicMax(pA,     e00); atomicMax(pA + 1, e01);
                    atomicMax(pB,     e10); atomicMax(pB + 1, e11);
                }
            }
        }
    }
}

// =====================================================================
// fc_c GEMM (K=128) with fused scatter-sum, 512 threads
// =====================================================================
#define FC_SMEM (1024 + 2 * 4 * PLANE)

__global__ __launch_bounds__(NT, 1)
void k_fcc(const float* __restrict__ A1,
           float* __restrict__ poolOut, float* __restrict__ cnt,
           const __nv_bfloat16* __restrict__ Whi, const __nv_bfloat16* __restrict__ Wlo,
           const float* __restrict__ bias) {
    extern __shared__ __align__(16) char smem[];
    float* biasS = (float*)smem;
    const int tid  = threadIdx.x, lane = tid & 31, wid = tid >> 5;
    const int m0   = blockIdx.x * 128;
    const int wm   = (wid & 3) * 32;
    const int wn   = (wid >> 2) * 32;
    const uint32_t sb = smem_u32(smem);

    if (tid < 128) biasS[tid] = bias[tid];

    const int aRow  = wm + (lane & 15);
    const int aCoff = (lane >> 4) * 8;
    const int bRow  = wn + (lane & 7) + ((lane >> 4) << 3);
    const int bCoff = ((lane >> 3) & 1) * 8;

    float acc[2][4][4] = {};

    auto loadA = [&](int ch, float4* vb) {
        #pragma unroll
        for (int j = 0; j < 4; j++) {
            int i = tid + j * NT;
            int r = i >> 4, c4 = (i & 15) << 2;
            vb[j] = *(const float4*)&A1[(size_t)(m0 + r) * 128 + ch * 64 + c4];
        }
    };
    auto storeA = [&](int set, const float4* vb) {
        const uint32_t base = SOFF + (uint32_t)set * SETSZ;
        #pragma unroll
        for (int j = 0; j < 4; j++) {
            int i = tid + j * NT;
            int r = i >> 4, c4 = (i & 15) << 2;
            float4 v = vb[j];
            __nv_bfloat162 h01, h23, l01, l23;
            h01.x = __float2bfloat16(v.x); h01.y = __float2bfloat16(v.y);
            h23.x = __float2bfloat16(v.z); h23.y = __float2bfloat16(v.w);
            l01.x = __float2bfloat16(v.x - __bfloat162float(h01.x));
            l01.y = __float2bfloat16(v.y - __bfloat162float(h01.y));
            l23.x = __float2bfloat16(v.z - __bfloat162float(h23.x));
            l23.y = __float2bfloat16(v.w - __bfloat162float(h23.y));
            uint32_t off = sw(r, c4 * 2);
            *(uint2*)(smem + base + off)         = make_uint2(b2u(h01), b2u(h23));
            *(uint2*)(smem + base + PLANE + off) = make_uint2(b2u(l01), b2u(l23));
        }
    };
    auto cpB = [&](int ch, int set) {
        const uint32_t base = sb + SOFF + (uint32_t)set * SETSZ + 2 * PLANE;
        #pragma unroll
        for (int j = 0; j < 2; j++) {
            int i = tid + j * NT;
            int r = i >> 3, c8 = (i & 7) << 3;
            uint32_t off = sw(r, c8 * 2);
            cp16(base + off,         &Whi[(size_t)r * 128 + ch * 64 + c8]);
            cp16(base + PLANE + off, &Wlo[(size_t)r * 128 + ch * 64 + c8]);
        }
        asm volatile("cp.async.commit_group;" ::: "memory");
    };
    auto mmaChunk = [&](uint32_t aBase, uint32_t bBase) {
        #pragma unroll
        for (int ks = 0; ks < 64; ks += 16) {
            uint32_t ah0[4], ah1[4], al0[4], al1[4];
            uint32_t c0 = (uint32_t)((ks + aCoff) * 2);
            ldsm4(ah0[0], ah0[1], ah0[2], ah0[3], sb + aBase + sw(aRow,      c0));
            ldsm4(ah1[0], ah1[1], ah1[2], ah1[3], sb + aBase + sw(aRow + 16, c0));
            ldsm4(al0[0], al0[1], al0[2], al0[3], sb + aBase + PLANE + sw(aRow,      c0));
            ldsm4(al1[0], al1[1], al1[2], al1[3], sb + aBase + PLANE + sw(aRow + 16, c0));
            uint32_t bh[4][2], bl[4][2];
            #pragma unroll
            for (int nf2 = 0; nf2 < 2; nf2++) {
                uint32_t ad = sw(bRow + nf2*16, (uint32_t)((ks + bCoff) * 2));
                ldsm4(bh[nf2*2][0], bh[nf2*2][1], bh[nf2*2+1][0], bh[nf2*2+1][1], sb + bBase + ad);
                ldsm4(bl[nf2*2][0], bl[nf2*2][1], bl[nf2*2+1][0], bl[nf2*2+1][1], sb + bBase + PLANE + ad);
            }
            MMA_TERMS(acc, ah0, ah1, al0, al1, bh, bl);
        }
    };

    float4 areg[4];
    loadA(0, areg);
    cpB(0, 0);
    #pragma unroll
    for (int ch = 0; ch < 2; ch++) {
        const int set = ch & 1;
        storeA(set, areg);
        asm volatile("cp.async.wait_group 0;" ::: "memory");
        __syncthreads();
        if (ch < 1) { cpB(1, 1); loadA(1, areg); }
        mmaChunk(SOFF + (uint32_t)set * SETSZ, SOFF + (uint32_t)set * SETSZ + 2*PLANE);
    }

    #pragma unroll
    for (int mf = 0; mf < 2; mf++) {
        const int m  = m0 + wm + mf*16 + (lane >> 2);
        const int bb = m >> 15;
        int cellA[3], cellB[3];
        #pragma unroll
        for (int k = 0; k < 3; k++) {
            cellA[k] = g_idx[k][m];
            cellB[k] = g_idx[k][m + 8];
        }
        #pragma unroll
        for (int nf = 0; nf < 4; nf++) {
            int n = wn + nf*8 + (lane & 3) * 2;
            float2 v0, v1;
            v0.x = acc[mf][nf][0] + biasS[n];
            v0.y = acc[mf][nf][1] + biasS[n+1];
            v1.x = acc[mf][nf][2] + biasS[n];
            v1.y = acc[mf][nf][3] + biasS[n+1];
            #pragma unroll
            for (int k = 0; k < 3; k++) {
                float* pA = &poolOut[((size_t)((k*B + bb)*R2) + cellA[k])*128 + n];
                float* pB = &poolOut[((size_t)((k*B + bb)*R2) + cellB[k])*128 + n];
                atomicAdd(pA,     v0.x); atomicAdd(pA + 1, v0.y);
                atomicAdd(pB,     v1.x); atomicAdd(pB + 1, v1.y);
                if (n == 0) {
                    atomicAdd(&cnt[(k*B + bb)*R2 + cellA[k]], 1.0f);
                    atomicAdd(&cnt[(k*B + bb)*R2 + cellB[k]], 1.0f);
                }
            }
        }
    }
}

// ---------------- finalize ----------------
__global__ void k_finalize(const float* __restrict__ pool, float* __restrict__ out) {
    int i = blockIdx.x * blockDim.x + threadIdx.x;
    if (i >= POOL_N) return;
    int cell = i & (R2 - 1);
    int f    = (i >> 14) & 127;
    int kb   = i >> 21;
    float cnt = g_cnt[kb * R2 + cell];
    out[i] = pool[(size_t)(kb * R2 + cell) * 128 + f] / fmaxf(cnt, 1.0f);
}

// ---------------- host orchestration ----------------
extern "C" void kernel_launch(void* const* d_in, const int* in_sizes, int n_in,
                              void* d_out, int out_size) {
    const float* p        = (const float*)d_in[0];
    const float* fc_pos_W = (const float*)d_in[1];
    const float* fc_pos_b = (const float*)d_in[2];
    const float* bW0      = (const float*)d_in[3];
    const float* bb0      = (const float*)d_in[4];
    const float* bW1      = (const float*)d_in[5];
    const float* bb1      = (const float*)d_in[6];
    const float* bWs      = (const float*)d_in[7];
    const float* fc_c_W   = (const float*)d_in[8];
    const float* fc_c_b   = (const float*)d_in[9];
    float* out = (float*)d_out;

    float*    gnet = nullptr; cudaGetSymbolAddress((void**)&gnet, g_net);
    uint32_t* pA   = nullptr; cudaGetSymbolAddress((void**)&pA,   g_poolA);
    uint32_t* pB   = nullptr; cudaGetSymbolAddress((void**)&pB,   g_poolB);
    float*    pM   = nullptr; cudaGetSymbolAddress((void**)&pM,   g_mean);
    float*    gcnt = nullptr; cudaGetSymbolAddress((void**)&gcnt, g_cnt);
    __nv_bfloat16* wt = nullptr; cudaGetSymbolAddress((void**)&wt, g_wt);

    cudaFuncSetAttribute(k_block<1, true >, cudaFuncAttributeMaxDynamicSharedMemorySize, FSMEM);
    cudaFuncSetAttribute(k_block<2, true >, cudaFuncAttributeMaxDynamicSharedMemorySize, FSMEM);
    cudaFuncSetAttribute(k_block<2, false>, cudaFuncAttributeMaxDynamicSharedMemorySize, FSMEM);
    cudaFuncSetAttribute(k_fcc,             cudaFuncAttributeMaxDynamicSharedMemorySize, FC_SMEM);

    const int TPB = 256;
    const int GG  = BT / 128;   // 512

    k_reset<<<(3 * (POOL_N / 4) + TPB - 1) / TPB, TPB>>>();
    k_index<<<BT / TPB, TPB>>>(p);
    k_wsplit<<<(425984 + TPB - 1) / TPB, TPB>>>(bW0, bW1, bWs, fc_c_W);

    auto W0hi = [&](int b){ return wt + (size_t)b * 65536; };
    auto W0lo = [&](int b){ return wt + (size_t)b * 65536 + 32768; };
    auto W1hi = [&](int b){ return wt + 327680 + (size_t)b * 32768; };
    auto W1lo = [&](int b){ return wt + 327680 + (size_t)b * 32768 + 16384; };
    auto WShi = [&](int b){ return wt + 491520 + (size_t)b * 65536; };
    auto WSlo = [&](int b){ return wt + 491520 + (size_t)b * 65536 + 32768; };
    const __nv_bfloat16* FChi = wt + 819200;
    const __nv_bfloat16* FClo = wt + 819200 + 16384;

    k_block<1, true><<<GG, NT, FSMEM>>>(nullptr, p, fc_pos_W, fc_pos_b, nullptr, pA, 1u,
                                        W0hi(0), W0lo(0), W1hi(0), W1lo(0), WShi(0), WSlo(0),
                                        bb0, bb1, gnet);

    uint32_t* pin  = pA;
    uint32_t* pout = pB;
    for (int blk = 1; blk < 5; blk++) {
        uint32_t tag = (uint32_t)blk + 1;
        if (blk < 4) {
            k_block<2, true><<<GG, NT, FSMEM>>>(gnet, nullptr, nullptr, nullptr, pin, pout, tag,
                                                W0hi(blk), W0lo(blk), W1hi(blk), W1lo(blk),
                                                WShi(blk), WSlo(blk),
                                                bb0 + blk*128, bb1 + blk*128, gnet);
        } else {
            k_block<2, false><<<GG, NT, FSMEM>>>(gnet, nullptr, nullptr, nullptr, pin, nullptr, 0u,
                                                 W0hi(blk), W0lo(blk), W1hi(blk), W1lo(blk),
                                                 WShi(blk), WSlo(blk),
                                                 bb0 + blk*128, bb1 + blk*128, gnet);
        }
        uint32_t* tmp = pin; pin = pout; pout = tmp;
    }

    k_fcc<<<GG, NT, FC_SMEM>>>(gnet, pM, gcnt, FChi, FClo, fc_c_b);

    k_finalize<<<(POOL_N + TPB - 1) / TPB, TPB>>>(pM, out);
}

// round 15
// speedup vs baseline: 1.0035x; 1.0035x over previous
#include <cuda_runtime.h>
#include <cuda_bf16.h>
#include <cstdint>

// ---------------- problem constants ----------------
#define B       2
#define T       32768
#define BT      (B*T)           // 65536
#define R2      16384
#define POOL_N  (3*B*R2*128)
#define CNT_N   (3*B*R2)

// ---------------- scratch ----------------
__device__ float    g_net[BT*128];
__device__ uint32_t g_poolA[POOL_N];   // tagged-max pools (ping-pong)
__device__ uint32_t g_poolB[POOL_N];
__device__ float    g_mean[POOL_N];    // scatter-mean accumulator
__device__ float    g_cnt[CNT_N];
__device__ int      g_idx[3][BT];
__device__ __nv_bfloat16 g_wt[851968];

// ---------------- helpers ----------------
__device__ __forceinline__ uint32_t smem_u32(const void* p) {
    uint32_t a;
    asm("{ .reg .u64 t; cvta.to.shared.u64 t, %1; cvt.u32.u64 %0, t; }" : "=r"(a) : "l"(p));
    return a;
}
__device__ __forceinline__ void ldsm4(uint32_t& r0, uint32_t& r1, uint32_t& r2, uint32_t& r3,
                                      uint32_t a) {
    asm volatile("ldmatrix.sync.aligned.m8n8.x4.shared.b16 {%0,%1,%2,%3}, [%4];"
        : "=r"(r0), "=r"(r1), "=r"(r2), "=r"(r3) : "r"(a));
}
__device__ __forceinline__ void mma16816(float* c, const uint32_t* a, uint32_t b0, uint32_t b1) {
    asm volatile("mma.sync.aligned.m16n8k16.row.col.f32.bf16.bf16.f32 "
        "{%0,%1,%2,%3}, {%4,%5,%6,%7}, {%8,%9}, {%0,%1,%2,%3};"
        : "+f"(c[0]), "+f"(c[1]), "+f"(c[2]), "+f"(c[3])
        : "r"(a[0]), "r"(a[1]), "r"(a[2]), "r"(a[3]), "r"(b0), "r"(b1));
}
__device__ __forceinline__ uint32_t b2u(__nv_bfloat162 v) {
    return *reinterpret_cast<uint32_t*>(&v);
}
__device__ __forceinline__ void cp16(uint32_t dst, const void* src) {
    asm volatile("cp.async.ca.shared.global [%0], [%1], 16;" :: "r"(dst), "l"(src));
}
// 128B-row swizzle
__device__ __forceinline__ uint32_t sw(int r, int cb) {
    return (uint32_t)(r * 128 + ((((cb >> 4) ^ (r & 7)) & 7) << 4) + (cb & 15));
}
// ---- tagged-max encoding: [31:29]=tag, [28:0]=order-preserving float enc >> 3
__device__ __forceinline__ uint32_t penc(float f, uint32_t tag) {
    uint32_t u = __float_as_uint(f);
    uint32_t e = (u >> 31) ? ~u : (u | 0x80000000u);
    return (tag << 29) | (e >> 3);
}
__device__ __forceinline__ float pdec(uint32_t w) {
    uint32_t e = (w & 0x1FFFFFFFu) << 3;
    return (e & 0x80000000u) ? __uint_as_float(e & 0x7FFFFFFFu)
                             : __uint_as_float(~e);
}

// ---------------- single upfront reset ----------------
__global__ void k_reset() {
    int i = blockIdx.x * blockDim.x + threadIdx.x;
    const int Q = POOL_N / 4;
    uint4 z; z.x = z.y = z.z = z.w = 0u;
    if (i < Q)               ((uint4*)g_poolA)[i]      = z;
    else if (i < 2*Q)        ((uint4*)g_poolB)[i - Q]  = z;
    else if (i < 3*Q)        ((uint4*)g_mean)[i - 2*Q] = z;
    if (i < CNT_N) g_cnt[i] = 0.0f;
}

// ---------------- index computation ----------------
__global__ void k_index(const float* __restrict__ p) {
    int t = blockIdx.x * blockDim.x + threadIdx.x;
    if (t >= BT) return;
    float x = p[t*3+0], y = p[t*3+1], z = p[t*3+2];
    float cu[3] = {x, x, y};
    float cv[3] = {z, y, z};
    const float hi = (float)(1.0 - 1e-5);
    #pragma unroll
    for (int k = 0; k < 3; k++) {
        float u = cu[k] / 1.101f + 0.5f;
        float v = cv[k] / 1.101f + 0.5f;
        u = fminf(fmaxf(u, 0.0f), hi);
        v = fminf(fmaxf(v, 0.0f), hi);
        g_idx[k][t] = (int)(u * 128.0f) + 128 * (int)(v * 128.0f);
    }
}

// ---------------- weight pre-split ----------------
__global__ void k_wsplit(const float* __restrict__ W0, const float* __restrict__ W1,
                         const float* __restrict__ Ws, const float* __restrict__ fcW) {
    int i = blockIdx.x * blockDim.x + threadIdx.x;
    if (i >= 425984) return;
    const float* src; int K, base, e;
    if (i < 163840)       { int blk = i / 32768;            e = i % 32768; K = 256; src = W0 + blk*32768; base = blk*65536; }
    else if (i < 245760)  { int j = i - 163840; int blk = j / 16384; e = j % 16384; K = 128; src = W1 + blk*16384; base = 327680 + blk*32768; }
    else if (i < 409600)  { int j = i - 245760; int blk = j / 32768; e = j % 32768; K = 256; src = Ws + blk*32768; base = 491520 + blk*65536; }
    else                  { e = i - 409600; K = 128; src = fcW; base = 819200; }
    int n = e / K, k = e % K;
    float v = src[(size_t)k * 128 + n];
    __nv_bfloat16 hi = __float2bfloat16(v);
    __nv_bfloat16 lo = __float2bfloat16(v - __bfloat162float(hi));
    g_wt[base + (size_t)n * K + k]           = hi;
    g_wt[base + (size_t)128 * K + n * K + k] = lo;
}

// =====================================================================
// Fused ResNet-block kernel, 512 threads (16 warps, 4x4 grid, m32n32)
// Convert/MMA overlap: per iter  sync -> prefetch -> MMA(ch) -> storeA(ch+1)
// =====================================================================
#define PLANE   16384
#define SETSZ   (4*PLANE)
#define SOFF    1024u
#define HIDOFF  (SOFF + 2*SETSZ)
#define FSMEM   (HIDOFF + 4*PLANE)               // 197632
#define NT      512

#define MMA_TERMS(acc, ah0, ah1, al0, al1, bh, bl)            \
    do {                                                      \
        _Pragma("unroll")                                     \
        for (int nf = 0; nf < 4; nf++) {                      \
            mma16816(acc[0][nf], ah0, bh[nf][0], bh[nf][1]);  \
            mma16816(acc[1][nf], ah1, bh[nf][0], bh[nf][1]);  \
        }                                                     \
        _Pragma("unroll")                                     \
        for (int nf = 0; nf < 4; nf++) {                      \
            mma16816(acc[0][nf], ah0, bl[nf][0], bl[nf][1]);  \
            mma16816(acc[1][nf], ah1, bl[nf][0], bl[nf][1]);  \
        }                                                     \
        _Pragma("unroll")                                     \
        for (int nf = 0; nf < 4; nf++) {                      \
            mma16816(acc[0][nf], al0, bh[nf][0], bh[nf][1]);  \
            mma16816(acc[1][nf], al1, bh[nf][0], bh[nf][1]);  \
        }                                                     \
    } while (0)

template<int ASRC, bool SCATTER>
__global__ __launch_bounds__(NT, 1)
void k_block(const float* __restrict__ A1,
             const float* __restrict__ P,
             const float* __restrict__ fcW,
             const float* __restrict__ fcb,
             const uint32_t* __restrict__ poolIn,
             uint32_t* __restrict__ poolOut,
             uint32_t tag,
             const __nv_bfloat16* __restrict__ W0hi, const __nv_bfloat16* __restrict__ W0lo,
             const __nv_bfloat16* __restrict__ W1hi, const __nv_bfloat16* __restrict__ W1lo,
             const __nv_bfloat16* __restrict__ WShi, const __nv_bfloat16* __restrict__ WSlo,
             const float* __restrict__ b0, const float* __restrict__ b1,
             float* __restrict__ C) {
    extern __shared__ __align__(16) char smem[];
    float* b0S = (float*)smem;
    float* b1S = (float*)(smem + 512);
    const int tid  = threadIdx.x, lane = tid & 31, wid = tid >> 5;
    const int m0   = blockIdx.x * 128;
    const int wm   = (wid & 3) * 32;
    const int wn   = (wid >> 2) * 32;
    const uint32_t sb = smem_u32(smem);

    if (tid < 128) { b0S[tid] = b0[tid]; b1S[tid] = b1[tid]; }

    const int aRow  = wm + (lane & 15);
    const int aCoff = (lane >> 4) * 8;
    const int bRow  = wn + (lane & 7) + ((lane >> 4) << 3);
    const int bCoff = ((lane >> 3) & 1) * 8;

    float acc[2][4][4] = {};

    auto loadA = [&](int ch, float4* vb) {
        const int K0 = ch * 64;
        #pragma unroll
        for (int j = 0; j < 4; j++) {
            int i = tid + j * NT;
            int r = i >> 4, c4 = (i & 15) << 2;
            int m = m0 + r;
            if (ASRC == 1) {
                float p0 = P[m*3+0], p1 = P[m*3+1], p2 = P[m*3+2];
                int cg = K0 + c4;
                float4 v;
                v.x = fmaf(p0, fcW[cg+0], fmaf(p1, fcW[256+cg+0], fmaf(p2, fcW[512+cg+0], fcb[cg+0])));
                v.y = fmaf(p0, fcW[cg+1], fmaf(p1, fcW[256+cg+1], fmaf(p2, fcW[512+cg+1], fcb[cg+1])));
                v.z = fmaf(p0, fcW[cg+2], fmaf(p1, fcW[256+cg+2], fmaf(p2, fcW[512+cg+2], fcb[cg+2])));
                v.w = fmaf(p0, fcW[cg+3], fmaf(p1, fcW[256+cg+3], fmaf(p2, fcW[512+cg+3], fcb[cg+3])));
                vb[j] = v;
            } else if (K0 >= 128) {
                int b = m >> 15;
                int c0 = (K0 - 128) + c4;
                float4 s; s.x = s.y = s.z = s.w = 0.0f;
                #pragma unroll
                for (int k = 0; k < 3; k++) {
                    int cell = g_idx[k][m];
                    uint4 pv = *(const uint4*)&poolIn[((size_t)((k*B + b)*R2) + cell)*128 + c0];
                    s.x += pdec(pv.x); s.y += pdec(pv.y);
                    s.z += pdec(pv.z); s.w += pdec(pv.w);
                }
                vb[j] = s;
            } else {
                vb[j] = *(const float4*)&A1[(size_t)m * 128 + K0 + c4];
            }
        }
    };
    auto storeA = [&](int set, const float4* vb, bool relu) {
        const uint32_t base = SOFF + (uint32_t)set * SETSZ;
        #pragma unroll
        for (int j = 0; j < 4; j++) {
            int i = tid + j * NT;
            int r = i >> 4, c4 = (i & 15) << 2;
            float4 v = vb[j];
            if (relu) {
                v.x = fmaxf(v.x, 0.f); v.y = fmaxf(v.y, 0.f);
                v.z = fmaxf(v.z, 0.f); v.w = fmaxf(v.w, 0.f);
            }
            __nv_bfloat162 h01, h23, l01, l23;
            h01.x = __float2bfloat16(v.x); h01.y = __float2bfloat16(v.y);
            h23.x = __float2bfloat16(v.z); h23.y = __float2bfloat16(v.w);
            l01.x = __float2bfloat16(v.x - __bfloat162float(h01.x));
            l01.y = __float2bfloat16(v.y - __bfloat162float(h01.y));
            l23.x = __float2bfloat16(v.z - __bfloat162float(h23.x));
            l23.y = __float2bfloat16(v.w - __bfloat162float(h23.y));
            uint32_t off = sw(r, c4 * 2);
            *(uint2*)(smem + base + off)         = make_uint2(b2u(h01), b2u(h23));
            *(uint2*)(smem + base + PLANE + off) = make_uint2(b2u(l01), b2u(l23));
        }
    };
    auto cpB = [&](const __nv_bfloat16* Whi, const __nv_bfloat16* Wlo, int K, int ch, int set) {
        const int K0 = ch * 64;
        const uint32_t base = sb + SOFF + (uint32_t)set * SETSZ + 2 * PLANE;
        #pragma unroll
        for (int j = 0; j < 2; j++) {
            int i = tid + j * NT;
            int r = i >> 3, c8 = (i & 7) << 3;
            uint32_t off = sw(r, c8 * 2);
            cp16(base + off,         &Whi[(size_t)r * K + K0 + c8]);
            cp16(base + PLANE + off, &Wlo[(size_t)r * K + K0 + c8]);
        }
        asm volatile("cp.async.commit_group;" ::: "memory");
    };
    auto mmaChunk = [&](uint32_t aBase, uint32_t bBase) {
        #pragma unroll
        for (int ks = 0; ks < 64; ks += 16) {
            uint32_t ah0[4], ah1[4], al0[4], al1[4];
            {
                uint32_t c0 = (uint32_t)((ks + aCoff) * 2);
                ldsm4(ah0[0], ah0[1], ah0[2], ah0[3], sb + aBase + sw(aRow,      c0));
                ldsm4(ah1[0], ah1[1], ah1[2], ah1[3], sb + aBase + sw(aRow + 16, c0));
                ldsm4(al0[0], al0[1], al0[2], al0[3], sb + aBase + PLANE + sw(aRow,      c0));
                ldsm4(al1[0], al1[1], al1[2], al1[3], sb + aBase + PLANE + sw(aRow + 16, c0));
            }
            uint32_t bh[4][2], bl[4][2];
            #pragma unroll
            for (int nf2 = 0; nf2 < 2; nf2++) {
                uint32_t ad = sw(bRow + nf2*16, (uint32_t)((ks + bCoff) * 2));
                ldsm4(bh[nf2*2][0], bh[nf2*2][1], bh[nf2*2+1][0], bh[nf2*2+1][1], sb + bBase + ad);
                ldsm4(bl[nf2*2][0], bl[nf2*2][1], bl[nf2*2+1][0], bl[nf2*2+1][1], sb + bBase + PLANE + ad);
            }
            MMA_TERMS(acc, ah0, ah1, al0, al1, bh, bl);
        }
    };

    // ================= phase W0 (K=256, relu A) =================
    float4 areg[4];
    loadA(0, areg);
    cpB(W0hi, W0lo, 256, 0, 0);
    storeA(0, areg, true);
    asm volatile("cp.async.wait_group 0;" ::: "memory");
    #pragma unroll
    for (int ch = 0; ch < 4; ch++) {
        const int set = ch & 1;
        __syncthreads();                       // set ch A+B visible to all
        if (ch < 3) {
            cpB(W0hi, W0lo, 256, ch + 1, set ^ 1);
            loadA(ch + 1, areg);
        } else {
            cpB(W1hi, W1lo, 128, 0, 0);
        }
        mmaChunk(SOFF + (uint32_t)set * SETSZ, SOFF + (uint32_t)set * SETSZ + 2*PLANE);
        if (ch < 3) storeA(set ^ 1, areg, true);   // overlaps other warps' MMA
        asm volatile("cp.async.wait_group 0;" ::: "memory");
    }
    __syncthreads();
    cpB(W1hi, W1lo, 128, 1, 1);
    loadA(0, areg);   // Ws chunk0 (raw) prefetch

    // hidden = relu(acc + b0) -> hidden planes; acc = b1
    #pragma unroll
    for (int mf = 0; mf < 2; mf++) {
        int mloc = wm + mf*16 + (lane >> 2);
        #pragma unroll
        for (int nf = 0; nf < 4; nf++) {
            int n = wn + nf*8 + (lane & 3) * 2;
            uint32_t hb = HIDOFF + (uint32_t)(n >> 6) * 2 * PLANE;
            #pragma unroll
            for (int q = 0; q < 2; q++) {
                int r = mloc + q * 8;
                float h0 = fmaxf(acc[mf][nf][2*q]   + b0S[n],   0.0f);
                float h1 = fmaxf(acc[mf][nf][2*q+1] + b0S[n+1], 0.0f);
                __nv_bfloat162 hh, ll;
                hh.x = __float2bfloat16(h0); hh.y = __float2bfloat16(h1);
                ll.x = __float2bfloat16(h0 - __bfloat162float(hh.x));
                ll.y = __float2bfloat16(h1 - __bfloat162float(hh.y));
                uint32_t off = sw(r, (n & 63) * 2);
                *(uint32_t*)(smem + hb + off)         = b2u(hh);
                *(uint32_t*)(smem + hb + PLANE + off) = b2u(ll);
            }
            #pragma unroll
            for (int q = 0; q < 4; q++) acc[mf][nf][q] = b1S[n + (q & 1)];
        }
    }
    asm volatile("cp.async.wait_group 0;" ::: "memory");
    __syncthreads();

    // ================= phase W1 (K=128, A = hidden planes) =================
    mmaChunk(HIDOFF,           SOFF + 2*PLANE);
    mmaChunk(HIDOFF + 2*PLANE, SOFF + SETSZ + 2*PLANE);
    __syncthreads();

    // ================= phase Ws (K=256, raw A), acc carries dx+b1 =================
    cpB(WShi, WSlo, 256, 0, 0);
    storeA(0, areg, false);
    asm volatile("cp.async.wait_group 0;" ::: "memory");
    #pragma unroll
    for (int ch = 0; ch < 4; ch++) {
        const int set = ch & 1;
        __syncthreads();
        if (ch < 3) {
            cpB(WShi, WSlo, 256, ch + 1, set ^ 1);
            loadA(ch + 1, areg);
        }
        mmaChunk(SOFF + (uint32_t)set * SETSZ, SOFF + (uint32_t)set * SETSZ + 2*PLANE);
        if (ch < 3) storeA(set ^ 1, areg, false);
        asm volatile("cp.async.wait_group 0;" ::: "memory");
    }

    // ---- epilogue: write net (+ tagged scatter-max)
    #pragma unroll
    for (int mf = 0; mf < 2; mf++) {
        const int m  = m0 + wm + mf*16 + (lane >> 2);
        const int bb = m >> 15;
        int cellA[3], cellB[3];
        if (SCATTER) {
            #pragma unroll
            for (int k = 0; k < 3; k++) {
                cellA[k] = g_idx[k][m];
                cellB[k] = g_idx[k][m + 8];
            }
        }
        #pragma unroll
        for (int nf = 0; nf < 4; nf++) {
            int n = wn + nf*8 + (lane & 3) * 2;
            float2 v0, v1;
            v0.x = acc[mf][nf][0]; v0.y = acc[mf][nf][1];
            v1.x = acc[mf][nf][2]; v1.y = acc[mf][nf][3];
            *(float2*)&C[(size_t)m * 128 + n]     = v0;
            *(float2*)&C[(size_t)(m+8) * 128 + n] = v1;
            if (SCATTER) {
                uint32_t e00 = penc(v0.x, tag), e01 = penc(v0.y, tag);
                uint32_t e10 = penc(v1.x, tag), e11 = penc(v1.y, tag);
                #pragma unroll
                for (int k = 0; k < 3; k++) {
                    uint32_t* pA = &poolOut[((size_t)((k*B + bb)*R2) + cellA[k])*128 + n];
                    uint32_t* pB = &poolOut[((size_t)((k*B + bb)*R2) + cellB[k])*128 + n];
                    atomicMax(pA,     e00); atomicMax(pA + 1, e01);
                    atomicMax(pB,     e10); atomicMax(pB + 1, e11);
                }
            }
        }
    }
}

// =====================================================================
// fc_c GEMM (K=128) with fused scatter-sum, 512 threads
// =====================================================================
#define FC_SMEM (1024 + 2 * 4 * PLANE)

__global__ __launch_bounds__(NT, 1)
void k_fcc(const float* __restrict__ A1,
           float* __restrict__ poolOut, float* __restrict__ cnt,
           const __nv_bfloat16* __restrict__ Whi, const __nv_bfloat16* __restrict__ Wlo,
           const float* __restrict__ bias) {
    extern __shared__ __align__(16) char smem[];
    float* biasS = (float*)smem;
    const int tid  = threadIdx.x, lane = tid & 31, wid = tid >> 5;
    const int m0   = blockIdx.x * 128;
    const int wm   = (wid & 3) * 32;
    const int wn   = (wid >> 2) * 32;
    const uint32_t sb = smem_u32(smem);

    if (tid < 128) biasS[tid] = bias[tid];

    const int aRow  = wm + (lane & 15);
    const int aCoff = (lane >> 4) * 8;
    const int bRow  = wn + (lane & 7) + ((lane >> 4) << 3);
    const int bCoff = ((lane >> 3) & 1) * 8;

    float acc[2][4][4] = {};

    auto loadA = [&](int ch, float4* vb) {
        #pragma unroll
        for (int j = 0; j < 4; j++) {
            int i = tid + j * NT;
            int r = i >> 4, c4 = (i & 15) << 2;
            vb[j] = *(const float4*)&A1[(size_t)(m0 + r) * 128 + ch * 64 + c4];
        }
    };
    auto storeA = [&](int set, const float4* vb) {
        const uint32_t base = SOFF + (uint32_t)set * SETSZ;
        #pragma unroll
        for (int j = 0; j < 4; j++) {
            int i = tid + j * NT;
            int r = i >> 4, c4 = (i & 15) << 2;
            float4 v = vb[j];
            __nv_bfloat162 h01, h23, l01, l23;
            h01.x = __float2bfloat16(v.x); h01.y = __float2bfloat16(v.y);
            h23.x = __float2bfloat16(v.z); h23.y = __float2bfloat16(v.w);
            l01.x = __float2bfloat16(v.x - __bfloat162float(h01.x));
            l01.y = __float2bfloat16(v.y - __bfloat162float(h01.y));
            l23.x = __float2bfloat16(v.z - __bfloat162float(h23.x));
            l23.y = __float2bfloat16(v.w - __bfloat162float(h23.y));
            uint32_t off = sw(r, c4 * 2);
            *(uint2*)(smem + base + off)         = make_uint2(b2u(h01), b2u(h23));
            *(uint2*)(smem + base + PLANE + off) = make_uint2(b2u(l01), b2u(l23));
        }
    };
    auto cpB = [&](int ch, int set) {
        const uint32_t base = sb + SOFF + (uint32_t)set * SETSZ + 2 * PLANE;
        #pragma unroll
        for (int j = 0; j < 2; j++) {
            int i = tid + j * NT;
            int r = i >> 3, c8 = (i & 7) << 3;
            uint32_t off = sw(r, c8 * 2);
            cp16(base + off,         &Whi[(size_t)r * 128 + ch * 64 + c8]);
            cp16(base + PLANE + off, &Wlo[(size_t)r * 128 + ch * 64 + c8]);
        }
        asm volatile("cp.async.commit_group;" ::: "memory");
    };
    auto mmaChunk = [&](uint32_t aBase, uint32_t bBase) {
        #pragma unroll
        for (int ks = 0; ks < 64; ks += 16) {
            uint32_t ah0[4], ah1[4], al0[4], al1[4];
            uint32_t c0 = (uint32_t)((ks + aCoff) * 2);
            ldsm4(ah0[0], ah0[1], ah0[2], ah0[3], sb + aBase + sw(aRow,      c0));
            ldsm4(ah1[0], ah1[1], ah1[2], ah1[3], sb + aBase + sw(aRow + 16, c0));
            ldsm4(al0[0], al0[1], al0[2], al0[3], sb + aBase + PLANE + sw(aRow,      c0));
            ldsm4(al1[0], al1[1], al1[2], al1[3], sb + aBase + PLANE + sw(aRow + 16, c0));
            uint32_t bh[4][2], bl[4][2];
            #pragma unroll
            for (int nf2 = 0; nf2 < 2; nf2++) {
                uint32_t ad = sw(bRow + nf2*16, (uint32_t)((ks + bCoff) * 2));
                ldsm4(bh[nf2*2][0], bh[nf2*2][1], bh[nf2*2+1][0], bh[nf2*2+1][1], sb + bBase + ad);
                ldsm4(bl[nf2*2][0], bl[nf2*2][1], bl[nf2*2+1][0], bl[nf2*2+1][1], sb + bBase + PLANE + ad);
            }
            MMA_TERMS(acc, ah0, ah1, al0, al1, bh, bl);
        }
    };

    float4 areg[4];
    loadA(0, areg);
    cpB(0, 0);
    storeA(0, areg);
    asm volatile("cp.async.wait_group 0;" ::: "memory");
    #pragma unroll
    for (int ch = 0; ch < 2; ch++) {
        const int set = ch & 1;
        __syncthreads();
        if (ch < 1) { cpB(1, 1); loadA(1, areg); }
        mmaChunk(SOFF + (uint32_t)set * SETSZ, SOFF + (uint32_t)set * SETSZ + 2*PLANE);
        if (ch < 1) storeA(1, areg);
        asm volatile("cp.async.wait_group 0;" ::: "memory");
    }

    #pragma unroll
    for (int mf = 0; mf < 2; mf++) {
        const int m  = m0 + wm + mf*16 + (lane >> 2);
        const int bb = m >> 15;
        int cellA[3], cellB[3];
        #pragma unroll
        for (int k = 0; k < 3; k++) {
            cellA[k] = g_idx[k][m];
            cellB[k] = g_idx[k][m + 8];
        }
        #pragma unroll
        for (int nf = 0; nf < 4; nf++) {
            int n = wn + nf*8 + (lane & 3) * 2;
            float2 v0, v1;
            v0.x = acc[mf][nf][0] + biasS[n];
            v0.y = acc[mf][nf][1] + biasS[n+1];
            v1.x = acc[mf][nf][2] + biasS[n];
            v1.y = acc[mf][nf][3] + biasS[n+1];
            #pragma unroll
            for (int k = 0; k < 3; k++) {
                float* pA = &poolOut[((size_t)((k*B + bb)*R2) + cellA[k])*128 + n];
                float* pB = &poolOut[((size_t)((k*B + bb)*R2) + cellB[k])*128 + n];
                atomicAdd(pA,     v0.x); atomicAdd(pA + 1, v0.y);
                atomicAdd(pB,     v1.x); atomicAdd(pB + 1, v1.y);
                if (n == 0) {
                    atomicAdd(&cnt[(k*B + bb)*R2 + cellA[k]], 1.0f);
                    atomicAdd(&cnt[(k*B + bb)*R2 + cellB[k]], 1.0f);
                }
            }
        }
    }
}

// ---------------- finalize ----------------
__global__ void k_finalize(const float* __restrict__ pool, float* __restrict__ out) {
    int i = blockIdx.x * blockDim.x + threadIdx.x;
    if (i >= POOL_N) return;
    int cell = i & (R2 - 1);
    int f    = (i >> 14) & 127;
    int kb   = i >> 21;
    float cnt = g_cnt[kb * R2 + cell];
    out[i] = pool[(size_t)(kb * R2 + cell) * 128 + f] / fmaxf(cnt, 1.0f);
}

// ---------------- host orchestration ----------------
extern "C" void kernel_launch(void* const* d_in, const int* in_sizes, int n_in,
                              void* d_out, int out_size) {
    const float* p        = (const float*)d_in[0];
    const float* fc_pos_W = (const float*)d_in[1];
    const float* fc_pos_b = (const float*)d_in[2];
    const float* bW0      = (const float*)d_in[3];
    const float* bb0      = (const float*)d_in[4];
    const float* bW1      = (const float*)d_in[5];
    const float* bb1      = (const float*)d_in[6];
    const float* bWs      = (const float*)d_in[7];
    const float* fc_c_W   = (const float*)d_in[8];
    const float* fc_c_b   = (const float*)d_in[9];
    float* out = (float*)d_out;

    float*    gnet = nullptr; cudaGetSymbolAddress((void**)&gnet, g_net);
    uint32_t* pA   = nullptr; cudaGetSymbolAddress((void**)&pA,   g_poolA);
    uint32_t* pB   = nullptr; cudaGetSymbolAddress((void**)&pB,   g_poolB);
    float*    pM   = nullptr; cudaGetSymbolAddress((void**)&pM,   g_mean);
    float*    gcnt = nullptr; cudaGetSymbolAddress((void**)&gcnt, g_cnt);
    __nv_bfloat16* wt = nullptr; cudaGetSymbolAddress((void**)&wt, g_wt);

    cudaFuncSetAttribute(k_block<1, true >, cudaFuncAttributeMaxDynamicSharedMemorySize, FSMEM);
    cudaFuncSetAttribute(k_block<2, true >, cudaFuncAttributeMaxDynamicSharedMemorySize, FSMEM);
    cudaFuncSetAttribute(k_block<2, false>, cudaFuncAttributeMaxDynamicSharedMemorySize, FSMEM);
    cudaFuncSetAttribute(k_fcc,             cudaFuncAttributeMaxDynamicSharedMemorySize, FC_SMEM);

    const int TPB = 256;
    const int GG  = BT / 128;   // 512

    k_reset<<<(3 * (POOL_N / 4) + TPB - 1) / TPB, TPB>>>();
    k_index<<<BT / TPB, TPB>>>(p);
    k_wsplit<<<(425984 + TPB - 1) / TPB, TPB>>>(bW0, bW1, bWs, fc_c_W);

    auto W0hi = [&](int b){ return wt + (size_t)b * 65536; };
    auto W0lo = [&](int b){ return wt + (size_t)b * 65536 + 32768; };
    auto W1hi = [&](int b){ return wt + 327680 + (size_t)b * 32768; };
    auto W1lo = [&](int b){ return wt + 327680 + (size_t)b * 32768 + 16384; };
    auto WShi = [&](int b){ return wt + 491520 + (size_t)b * 65536; };
    auto WSlo = [&](int b){ return wt + 491520 + (size_t)b * 65536 + 32768; };
    const __nv_bfloat16* FChi = wt + 819200;
    const __nv_bfloat16* FClo = wt + 819200 + 16384;

    k_block<1, true><<<GG, NT, FSMEM>>>(nullptr, p, fc_pos_W, fc_pos_b, nullptr, pA, 1u,
                                        W0hi(0), W0lo(0), W1hi(0), W1lo(0), WShi(0), WSlo(0),
                                        bb0, bb1, gnet);

    uint32_t* pin  = pA;
    uint32_t* pout = pB;
    for (int blk = 1; blk < 5; blk++) {
        uint32_t tag = (uint32_t)blk + 1;
        if (blk < 4) {
            k_block<2, true><<<GG, NT, FSMEM>>>(gnet, nullptr, nullptr, nullptr, pin, pout, tag,
                                                W0hi(blk), W0lo(blk), W1hi(blk), W1lo(blk),
                                                WShi(blk), WSlo(blk),
                                                bb0 + blk*128, bb1 + blk*128, gnet);
        } else {
            k_block<2, false><<<GG, NT, FSMEM>>>(gnet, nullptr, nullptr, nullptr, pin, nullptr, 0u,
                                                 W0hi(blk), W0lo(blk), W1hi(blk), W1lo(blk),
                                                 WShi(blk), WSlo(blk),
                                                 bb0 + blk*128, bb1 + blk*128, gnet);
        }
        uint32_t* tmp = pin; pin = pout; pout = tmp;
    }

    k_fcc<<<GG, NT, FC_SMEM>>>(gnet, pM, gcnt, FChi, FClo, fc_c_b);

    k_finalize<<<(POOL_N + TPB - 1) / TPB, TPB>>>(pM, out);
}

// round 16
// speedup vs baseline: 1.0121x; 1.0086x over previous
#include <cuda_runtime.h>
#include <cuda_bf16.h>
#include <cstdint>

// ---------------- problem constants ----------------
#define B       2
#define T       32768
#define BT      (B*T)           // 65536
#define R2      16384
#define POOL_N  (3*B*R2*128)
#define CNT_N   (3*B*R2)

// ---------------- scratch ----------------
__device__ float    g_net[BT*128];
__device__ uint32_t g_poolA[POOL_N];   // tagged-max pools (ping-pong)
__device__ uint32_t g_poolB[POOL_N];
__device__ float    g_mean[POOL_N];    // scatter-mean accumulator
__device__ float    g_cnt[CNT_N];
__device__ int      g_idx[3][BT];
__device__ __nv_bfloat16 g_wt[851968];

// ---------------- helpers ----------------
__device__ __forceinline__ uint32_t smem_u32(const void* p) {
    uint32_t a;
    asm("{ .reg .u64 t; cvta.to.shared.u64 t, %1; cvt.u32.u64 %0, t; }" : "=r"(a) : "l"(p));
    return a;
}
__device__ __forceinline__ void ldsm4(uint32_t& r0, uint32_t& r1, uint32_t& r2, uint32_t& r3,
                                      uint32_t a) {
    asm volatile("ldmatrix.sync.aligned.m8n8.x4.shared.b16 {%0,%1,%2,%3}, [%4];"
        : "=r"(r0), "=r"(r1), "=r"(r2), "=r"(r3) : "r"(a));
}
// NOTE: non-volatile — pure register op; ptxas may reschedule for latency hiding.
__device__ __forceinline__ void mma16816(float* c, const uint32_t* a, uint32_t b0, uint32_t b1) {
    asm("mma.sync.aligned.m16n8k16.row.col.f32.bf16.bf16.f32 "
        "{%0,%1,%2,%3}, {%4,%5,%6,%7}, {%8,%9}, {%0,%1,%2,%3};"
        : "+f"(c[0]), "+f"(c[1]), "+f"(c[2]), "+f"(c[3])
        : "r"(a[0]), "r"(a[1]), "r"(a[2]), "r"(a[3]), "r"(b0), "r"(b1));
}
__device__ __forceinline__ uint32_t b2u(__nv_bfloat162 v) {
    return *reinterpret_cast<uint32_t*>(&v);
}
__device__ __forceinline__ void cp16(uint32_t dst, const void* src) {
    asm volatile("cp.async.ca.shared.global [%0], [%1], 16;" :: "r"(dst), "l"(src));
}
// 128B-row swizzle
__device__ __forceinline__ uint32_t sw(int r, int cb) {
    return (uint32_t)(r * 128 + ((((cb >> 4) ^ (r & 7)) & 7) << 4) + (cb & 15));
}
// ---- tagged-max encoding
__device__ __forceinline__ uint32_t penc(float f, uint32_t tag) {
    uint32_t u = __float_as_uint(f);
    uint32_t e = (u >> 31) ? ~u : (u | 0x80000000u);
    return (tag << 29) | (e >> 3);
}
__device__ __forceinline__ float pdec(uint32_t w) {
    uint32_t e = (w & 0x1FFFFFFFu) << 3;
    return (e & 0x80000000u) ? __uint_as_float(e & 0x7FFFFFFFu)
                             : __uint_as_float(~e);
}

// ---------------- single upfront reset ----------------
__global__ void k_reset() {
    int i = blockIdx.x * blockDim.x + threadIdx.x;
    const int Q = POOL_N / 4;
    uint4 z; z.x = z.y = z.z = z.w = 0u;
    if (i < Q)               ((uint4*)g_poolA)[i]      = z;
    else if (i < 2*Q)        ((uint4*)g_poolB)[i - Q]  = z;
    else if (i < 3*Q)        ((uint4*)g_mean)[i - 2*Q] = z;
    if (i < CNT_N) g_cnt[i] = 0.0f;
}

// ---------------- index computation ----------------
__global__ void k_index(const float* __restrict__ p) {
    int t = blockIdx.x * blockDim.x + threadIdx.x;
    if (t >= BT) return;
    float x = p[t*3+0], y = p[t*3+1], z = p[t*3+2];
    float cu[3] = {x, x, y};
    float cv[3] = {z, y, z};
    const float hi = (float)(1.0 - 1e-5);
    #pragma unroll
    for (int k = 0; k < 3; k++) {
        float u = cu[k] / 1.101f + 0.5f;
        float v = cv[k] / 1.101f + 0.5f;
        u = fminf(fmaxf(u, 0.0f), hi);
        v = fminf(fmaxf(v, 0.0f), hi);
        g_idx[k][t] = (int)(u * 128.0f) + 128 * (int)(v * 128.0f);
    }
}

// ---------------- weight pre-split ----------------
__global__ void k_wsplit(const float* __restrict__ W0, const float* __restrict__ W1,
                         const float* __restrict__ Ws, const float* __restrict__ fcW) {
    int i = blockIdx.x * blockDim.x + threadIdx.x;
    if (i >= 425984) return;
    const float* src; int K, base, e;
    if (i < 163840)       { int blk = i / 32768;            e = i % 32768; K = 256; src = W0 + blk*32768; base = blk*65536; }
    else if (i < 245760)  { int j = i - 163840; int blk = j / 16384; e = j % 16384; K = 128; src = W1 + blk*16384; base = 327680 + blk*32768; }
    else if (i < 409600)  { int j = i - 245760; int blk = j / 32768; e = j % 32768; K = 256; src = Ws + blk*32768; base = 491520 + blk*65536; }
    else                  { e = i - 409600; K = 128; src = fcW; base = 819200; }
    int n = e / K, k = e % K;
    float v = src[(size_t)k * 128 + n];
    __nv_bfloat16 hi = __float2bfloat16(v);
    __nv_bfloat16 lo = __float2bfloat16(v - __bfloat162float(hi));
    g_wt[base + (size_t)n * K + k]           = hi;
    g_wt[base + (size_t)128 * K + n * K + k] = lo;
}

// =====================================================================
// Fused ResNet-block kernel, 512 threads (16 warps, 4x4 grid, m32n32)
// =====================================================================
#define PLANE   16384
#define SETSZ   (4*PLANE)
#define SOFF    1024u
#define HIDOFF  (SOFF + 2*SETSZ)
#define FSMEM   (HIDOFF + 4*PLANE)               // 197632
#define NT      512

#define MMA_TERMS(acc, ah0, ah1, al0, al1, bh, bl)            \
    do {                                                      \
        _Pragma("unroll")                                     \
        for (int nf = 0; nf < 4; nf++) {                      \
            mma16816(acc[0][nf], ah0, bh[nf][0], bh[nf][1]);  \
            mma16816(acc[1][nf], ah1, bh[nf][0], bh[nf][1]);  \
        }                                                     \
        _Pragma("unroll")                                     \
        for (int nf = 0; nf < 4; nf++) {                      \
            mma16816(acc[0][nf], ah0, bl[nf][0], bl[nf][1]);  \
            mma16816(acc[1][nf], ah1, bl[nf][0], bl[nf][1]);  \
        }                                                     \
        _Pragma("unroll")                                     \
        for (int nf = 0; nf < 4; nf++) {                      \
            mma16816(acc[0][nf], al0, bh[nf][0], bh[nf][1]);  \
            mma16816(acc[1][nf], al1, bh[nf][0], bh[nf][1]);  \
        }                                                     \
    } while (0)

struct Frag {
    uint32_t ah0[4], ah1[4], al0[4], al1[4];
    uint32_t bh[4][2], bl[4][2];
};

template<int ASRC, bool SCATTER>
__global__ __launch_bounds__(NT, 1)
void k_block(const float* __restrict__ A1,
             const float* __restrict__ P,
             const float* __restrict__ fcW,
             const float* __restrict__ fcb,
             const uint32_t* __restrict__ poolIn,
             uint32_t* __restrict__ poolOut,
             uint32_t tag,
             const __nv_bfloat16* __restrict__ W0hi, const __nv_bfloat16* __restrict__ W0lo,
             const __nv_bfloat16* __restrict__ W1hi, const __nv_bfloat16* __restrict__ W1lo,
             const __nv_bfloat16* __restrict__ WShi, const __nv_bfloat16* __restrict__ WSlo,
             const float* __restrict__ b0, const float* __restrict__ b1,
             float* __restrict__ C) {
    extern __shared__ __align__(16) char smem[];
    float* b0S = (float*)smem;
    float* b1S = (float*)(smem + 512);
    const int tid  = threadIdx.x, lane = tid & 31, wid = tid >> 5;
    const int m0   = blockIdx.x * 128;
    const int wm   = (wid & 3) * 32;
    const int wn   = (wid >> 2) * 32;
    const uint32_t sb = smem_u32(smem);

    if (tid < 128) { b0S[tid] = b0[tid]; b1S[tid] = b1[tid]; }

    const int aRow  = wm + (lane & 15);
    const int aCoff = (lane >> 4) * 8;
    const int bRow  = wn + (lane & 7) + ((lane >> 4) << 3);
    const int bCoff = ((lane >> 3) & 1) * 8;

    float acc[2][4][4] = {};

    auto loadA = [&](int ch, float4* vb) {
        const int K0 = ch * 64;
        #pragma unroll
        for (int j = 0; j < 4; j++) {
            int i = tid + j * NT;
            int r = i >> 4, c4 = (i & 15) << 2;
            int m = m0 + r;
            if (ASRC == 1) {
                float p0 = P[m*3+0], p1 = P[m*3+1], p2 = P[m*3+2];
                int cg = K0 + c4;
                float4 v;
                v.x = fmaf(p0, fcW[cg+0], fmaf(p1, fcW[256+cg+0], fmaf(p2, fcW[512+cg+0], fcb[cg+0])));
                v.y = fmaf(p0, fcW[cg+1], fmaf(p1, fcW[256+cg+1], fmaf(p2, fcW[512+cg+1], fcb[cg+1])));
                v.z = fmaf(p0, fcW[cg+2], fmaf(p1, fcW[256+cg+2], fmaf(p2, fcW[512+cg+2], fcb[cg+2])));
                v.w = fmaf(p0, fcW[cg+3], fmaf(p1, fcW[256+cg+3], fmaf(p2, fcW[512+cg+3], fcb[cg+3])));
                vb[j] = v;
            } else if (K0 >= 128) {
                int b = m >> 15;
                int c0 = (K0 - 128) + c4;
                float4 s; s.x = s.y = s.z = s.w = 0.0f;
                #pragma unroll
                for (int k = 0; k < 3; k++) {
                    int cell = g_idx[k][m];
                    uint4 pv = *(const uint4*)&poolIn[((size_t)((k*B + b)*R2) + cell)*128 + c0];
                    s.x += pdec(pv.x); s.y += pdec(pv.y);
                    s.z += pdec(pv.z); s.w += pdec(pv.w);
                }
                vb[j] = s;
            } else {
                vb[j] = *(const float4*)&A1[(size_t)m * 128 + K0 + c4];
            }
        }
    };
    auto storeA = [&](int set, const float4* vb, bool relu) {
        const uint32_t base = SOFF + (uint32_t)set * SETSZ;
        #pragma unroll
        for (int j = 0; j < 4; j++) {
            int i = tid + j * NT;
            int r = i >> 4, c4 = (i & 15) << 2;
            float4 v = vb[j];
            if (relu) {
                v.x = fmaxf(v.x, 0.f); v.y = fmaxf(v.y, 0.f);
                v.z = fmaxf(v.z, 0.f); v.w = fmaxf(v.w, 0.f);
            }
            __nv_bfloat162 h01, h23, l01, l23;
            h01.x = __float2bfloat16(v.x); h01.y = __float2bfloat16(v.y);
            h23.x = __float2bfloat16(v.z); h23.y = __float2bfloat16(v.w);
            l01.x = __float2bfloat16(v.x - __bfloat162float(h01.x));
            l01.y = __float2bfloat16(v.y - __bfloat162float(h01.y));
            l23.x = __float2bfloat16(v.z - __bfloat162float(h23.x));
            l23.y = __float2bfloat16(v.w - __bfloat162float(h23.y));
            uint32_t off = sw(r, c4 * 2);
            *(uint2*)(smem + base + off)         = make_uint2(b2u(h01), b2u(h23));
            *(uint2*)(smem + base + PLANE + off) = make_uint2(b2u(l01), b2u(l23));
        }
    };
    auto cpB = [&](const __nv_bfloat16* Whi, const __nv_bfloat16* Wlo, int K, int ch, int set) {
        const int K0 = ch * 64;
        const uint32_t base = sb + SOFF + (uint32_t)set * SETSZ + 2 * PLANE;
        #pragma unroll
        for (int j = 0; j < 2; j++) {
            int i = tid + j * NT;
            int r = i >> 3, c8 = (i & 7) << 3;
            uint32_t off = sw(r, c8 * 2);
            cp16(base + off,         &Whi[(size_t)r * K + K0 + c8]);
            cp16(base + PLANE + off, &Wlo[(size_t)r * K + K0 + c8]);
        }
        asm volatile("cp.async.commit_group;" ::: "memory");
    };
    // fragment fetch for one k-step
    auto ldFrag = [&](Frag& f, uint32_t aBase, uint32_t bBase, int ks) {
        uint32_t c0 = (uint32_t)((ks + aCoff) * 2);
        ldsm4(f.ah0[0], f.ah0[1], f.ah0[2], f.ah0[3], sb + aBase + sw(aRow,      c0));
        ldsm4(f.ah1[0], f.ah1[1], f.ah1[2], f.ah1[3], sb + aBase + sw(aRow + 16, c0));
        ldsm4(f.al0[0], f.al0[1], f.al0[2], f.al0[3], sb + aBase + PLANE + sw(aRow,      c0));
        ldsm4(f.al1[0], f.al1[1], f.al1[2], f.al1[3], sb + aBase + PLANE + sw(aRow + 16, c0));
        #pragma unroll
        for (int nf2 = 0; nf2 < 2; nf2++) {
            uint32_t ad = sw(bRow + nf2*16, (uint32_t)((ks + bCoff) * 2));
            ldsm4(f.bh[nf2*2][0], f.bh[nf2*2][1], f.bh[nf2*2+1][0], f.bh[nf2*2+1][1], sb + bBase + ad);
            ldsm4(f.bl[nf2*2][0], f.bl[nf2*2][1], f.bl[nf2*2+1][0], f.bl[nf2*2+1][1], sb + bBase + PLANE + ad);
        }
    };
    // software-pipelined chunk: frag(ks+1) fetched before MMAs of ks
    auto mmaChunk = [&](uint32_t aBase, uint32_t bBase) {
        Frag fr[2];
        ldFrag(fr[0], aBase, bBase, 0);
        #pragma unroll
        for (int i = 0; i < 4; i++) {
            if (i < 3) ldFrag(fr[(i + 1) & 1], aBase, bBase, (i + 1) * 16);
            Frag& f = fr[i & 1];
            MMA_TERMS(acc, f.ah0, f.ah1, f.al0, f.al1, f.bh, f.bl);
        }
    };

    // ================= phase W0 (K=256, relu A) =================
    float4 areg[4];
    loadA(0, areg);
    cpB(W0hi, W0lo, 256, 0, 0);
    storeA(0, areg, true);
    asm volatile("cp.async.wait_group 0;" ::: "memory");
    #pragma unroll
    for (int ch = 0; ch < 4; ch++) {
        const int set = ch & 1;
        __syncthreads();
        if (ch < 3) {
            cpB(W0hi, W0lo, 256, ch + 1, set ^ 1);
            loadA(ch + 1, areg);
        } else {
            cpB(W1hi, W1lo, 128, 0, 0);
        }
        mmaChunk(SOFF + (uint32_t)set * SETSZ, SOFF + (uint32_t)set * SETSZ + 2*PLANE);
        if (ch < 3) storeA(set ^ 1, areg, true);
        asm volatile("cp.async.wait_group 0;" ::: "memory");
    }
    __syncthreads();
    cpB(W1hi, W1lo, 128, 1, 1);
    loadA(0, areg);   // Ws chunk0 prefetch

    // hidden = relu(acc + b0) -> hidden planes; acc = b1
    #pragma unroll
    for (int mf = 0; mf < 2; mf++) {
        int mloc = wm + mf*16 + (lane >> 2);
        #pragma unroll
        for (int nf = 0; nf < 4; nf++) {
            int n = wn + nf*8 + (lane & 3) * 2;
            uint32_t hb = HIDOFF + (uint32_t)(n >> 6) * 2 * PLANE;
            #pragma unroll
            for (int q = 0; q < 2; q++) {
                int r = mloc + q * 8;
                float h0 = fmaxf(acc[mf][nf][2*q]   + b0S[n],   0.0f);
                float h1 = fmaxf(acc[mf][nf][2*q+1] + b0S[n+1], 0.0f);
                __nv_bfloat162 hh, ll;
                hh.x = __float2bfloat16(h0); hh.y = __float2bfloat16(h1);
                ll.x = __float2bfloat16(h0 - __bfloat162float(hh.x));
                ll.y = __float2bfloat16(h1 - __bfloat162float(hh.y));
                uint32_t off = sw(r, (n & 63) * 2);
                *(uint32_t*)(smem + hb + off)         = b2u(hh);
                *(uint32_t*)(smem + hb + PLANE + off) = b2u(ll);
            }
            #pragma unroll
            for (int q = 0; q < 4; q++) acc[mf][nf][q] = b1S[n + (q & 1)];
        }
    }
    asm volatile("cp.async.wait_group 0;" ::: "memory");
    __syncthreads();

    // ================= phase W1 (K=128, A = hidden planes) =================
    mmaChunk(HIDOFF,           SOFF + 2*PLANE);
    mmaChunk(HIDOFF + 2*PLANE, SOFF + SETSZ + 2*PLANE);
    __syncthreads();

    // ================= phase Ws (K=256, raw A) =================
    cpB(WShi, WSlo, 256, 0, 0);
    storeA(0, areg, false);
    asm volatile("cp.async.wait_group 0;" ::: "memory");
    #pragma unroll
    for (int ch = 0; ch < 4; ch++) {
        const int set = ch & 1;
        __syncthreads();
        if (ch < 3) {
            cpB(WShi, WSlo, 256, ch + 1, set ^ 1);
            loadA(ch + 1, areg);
        }
        mmaChunk(SOFF + (uint32_t)set * SETSZ, SOFF + (uint32_t)set * SETSZ + 2*PLANE);
        if (ch < 3) storeA(set ^ 1, areg, false);
        asm volatile("cp.async.wait_group 0;" ::: "memory");
    }

    // ---- epilogue: write net (+ tagged scatter-max)
    #pragma unroll
    for (int mf = 0; mf < 2; mf++) {
        const int m  = m0 + wm + mf*16 + (lane >> 2);
        const int bb = m >> 15;
        int cellA[3], cellB[3];
        if (SCATTER) {
            #pragma unroll
            for (int k = 0; k < 3; k++) {
                cellA[k] = g_idx[k][m];
                cellB[k] = g_idx[k][m + 8];
            }
        }
        #pragma unroll
        for (int nf = 0; nf < 4; nf++) {
            int n = wn + nf*8 + (lane & 3) * 2;
            float2 v0, v1;
            v0.x = acc[mf][nf][0]; v0.y = acc[mf][nf][1];
            v1.x = acc[mf][nf][2]; v1.y = acc[mf][nf][3];
            *(float2*)&C[(size_t)m * 128 + n]     = v0;
            *(float2*)&C[(size_t)(m+8) * 128 + n] = v1;
            if (SCATTER) {
                uint32_t e00 = penc(v0.x, tag), e01 = penc(v0.y, tag);
                uint32_t e10 = penc(v1.x, tag), e11 = penc(v1.y, tag);
                #pragma unroll
                for (int k = 0; k < 3; k++) {
                    uint32_t* pA = &poolOut[((size_t)((k*B + bb)*R2) + cellA[k])*128 + n];
                    uint32_t* pB = &poolOut[((size_t)((k*B + bb)*R2) + cellB[k])*128 + n];
                    atomicMax(pA,     e00); atomicMax(pA + 1, e01);
                    atomicMax(pB,     e10); atomicMax(pB + 1, e11);
                }
            }
        }
    }
}

// =====================================================================
// fc_c GEMM (K=128) with fused scatter-sum, 512 threads
// =====================================================================
#define FC_SMEM (1024 + 2 * 4 * PLANE)

__global__ __launch_bounds__(NT, 1)
void k_fcc(const float* __restrict__ A1,
           float* __restrict__ poolOut, float* __restrict__ cnt,
           const __nv_bfloat16* __restrict__ Whi, const __nv_bfloat16* __restrict__ Wlo,
           const float* __restrict__ bias) {
    extern __shared__ __align__(16) char smem[];
    float* biasS = (float*)smem;
    const int tid  = threadIdx.x, lane = tid & 31, wid = tid >> 5;
    const int m0   = blockIdx.x * 128;
    const int wm   = (wid & 3) * 32;
    const int wn   = (wid >> 2) * 32;
    const uint32_t sb = smem_u32(smem);

    if (tid < 128) biasS[tid] = bias[tid];

    const int aRow  = wm + (lane & 15);
    const int aCoff = (lane >> 4) * 8;
    const int bRow  = wn + (lane & 7) + ((lane >> 4) << 3);
    const int bCoff = ((lane >> 3) & 1) * 8;

    float acc[2][4][4] = {};

    auto loadA = [&](int ch, float4* vb) {
        #pragma unroll
        for (int j = 0; j < 4; j++) {
            int i = tid + j * NT;
            int r = i >> 4, c4 = (i & 15) << 2;
            vb[j] = *(const float4*)&A1[(size_t)(m0 + r) * 128 + ch * 64 + c4];
        }
    };
    auto storeA = [&](int set, const float4* vb) {
        const uint32_t base = SOFF + (uint32_t)set * SETSZ;
        #pragma unroll
        for (int j = 0; j < 4; j++) {
            int i = tid + j * NT;
            int r = i >> 4, c4 = (i & 15) << 2;
            float4 v = vb[j];
            __nv_bfloat162 h01, h23, l01, l23;
            h01.x = __float2bfloat16(v.x); h01.y = __float2bfloat16(v.y);
            h23.x = __float2bfloat16(v.z); h23.y = __float2bfloat16(v.w);
            l01.x = __float2bfloat16(v.x - __bfloat162float(h01.x));
            l01.y = __float2bfloat16(v.y - __bfloat162float(h01.y));
            l23.x = __float2bfloat16(v.z - __bfloat162float(h23.x));
            l23.y = __float2bfloat16(v.w - __bfloat162float(h23.y));
            uint32_t off = sw(r, c4 * 2);
            *(uint2*)(smem + base + off)         = make_uint2(b2u(h01), b2u(h23));
            *(uint2*)(smem + base + PLANE + off) = make_uint2(b2u(l01), b2u(l23));
        }
    };
    auto cpB = [&](int ch, int set) {
        const uint32_t base = sb + SOFF + (uint32_t)set * SETSZ + 2 * PLANE;
        #pragma unroll
        for (int j = 0; j < 2; j++) {
            int i = tid + j * NT;
            int r = i >> 3, c8 = (i & 7) << 3;
            uint32_t off = sw(r, c8 * 2);
            cp16(base + off,         &Whi[(size_t)r * 128 + ch * 64 + c8]);
            cp16(base + PLANE + off, &Wlo[(size_t)r * 128 + ch * 64 + c8]);
        }
        asm volatile("cp.async.commit_group;" ::: "memory");
    };
    auto ldFrag = [&](Frag& f, uint32_t aBase, uint32_t bBase, int ks) {
        uint32_t c0 = (uint32_t)((ks + aCoff) * 2);
        ldsm4(f.ah0[0], f.ah0[1], f.ah0[2], f.ah0[3], sb + aBase + sw(aRow,      c0));
        ldsm4(f.ah1[0], f.ah1[1], f.ah1[2], f.ah1[3], sb + aBase + sw(aRow + 16, c0));
        ldsm4(f.al0[0], f.al0[1], f.al0[2], f.al0[3], sb + aBase + PLANE + sw(aRow,      c0));
        ldsm4(f.al1[0], f.al1[1], f.al1[2], f.al1[3], sb + aBase + PLANE + sw(aRow + 16, c0));
        #pragma unroll
        for (int nf2 = 0; nf2 < 2; nf2++) {
            uint32_t ad = sw(bRow + nf2*16, (uint32_t)((ks + bCoff) * 2));
            ldsm4(f.bh[nf2*2][0], f.bh[nf2*2][1], f.bh[nf2*2+1][0], f.bh[nf2*2+1][1], sb + bBase + ad);
            ldsm4(f.bl[nf2*2][0], f.bl[nf2*2][1], f.bl[nf2*2+1][0], f.bl[nf2*2+1][1], sb + bBase + PLANE + ad);
        }
    };
    auto mmaChunk = [&](uint32_t aBase, uint32_t bBase) {
        Frag fr[2];
        ldFrag(fr[0], aBase, bBase, 0);
        #pragma unroll
        for (int i = 0; i < 4; i++) {
            if (i < 3) ldFrag(fr[(i + 1) & 1], aBase, bBase, (i + 1) * 16);
            Frag& f = fr[i & 1];
            MMA_TERMS(acc, f.ah0, f.ah1, f.al0, f.al1, f.bh, f.bl);
        }
    };

    float4 areg[4];
    loadA(0, areg);
    cpB(0, 0);
    storeA(0, areg);
    asm volatile("cp.async.wait_group 0;" ::: "memory");
    #pragma unroll
    for (int ch = 0; ch < 2; ch++) {
        const int set = ch & 1;
        __syncthreads();
        if (ch < 1) { cpB(1, 1); loadA(1, areg); }
        mmaChunk(SOFF + (uint32_t)set * SETSZ, SOFF + (uint32_t)set * SETSZ + 2*PLANE);
        if (ch < 1) storeA(1, areg);
        asm volatile("cp.async.wait_group 0;" ::: "memory");
    }

    #pragma unroll
    for (int mf = 0; mf < 2; mf++) {
        const int m  = m0 + wm + mf*16 + (lane >> 2);
        const int bb = m >> 15;
        int cellA[3], cellB[3];
        #pragma unroll
        for (int k = 0; k < 3; k++) {
            cellA[k] = g_idx[k][m];
            cellB[k] = g_idx[k][m + 8];
        }
        #pragma unroll
        for (int nf = 0; nf < 4; nf++) {
            int n = wn + nf*8 + (lane & 3) * 2;
            float2 v0, v1;
            v0.x = acc[mf][nf][0] + biasS[n];
            v0.y = acc[mf][nf][1] + biasS[n+1];
            v1.x = acc[mf][nf][2] + biasS[n];
            v1.y = acc[mf][nf][3] + biasS[n+1];
            #pragma unroll
            for (int k = 0; k < 3; k++) {
                float* pA = &poolOut[((size_t)((k*B + bb)*R2) + cellA[k])*128 + n];
                float* pB = &poolOut[((size_t)((k*B + bb)*R2) + cellB[k])*128 + n];
                atomicAdd(pA,     v0.x); atomicAdd(pA + 1, v0.y);
                atomicAdd(pB,     v1.x); atomicAdd(pB + 1, v1.y);
                if (n == 0) {
                    atomicAdd(&cnt[(k*B + bb)*R2 + cellA[k]], 1.0f);
                    atomicAdd(&cnt[(k*B + bb)*R2 + cellB[k]], 1.0f);
                }
            }
        }
    }
}

// ---------------- finalize ----------------
__global__ void k_finalize(const float* __restrict__ pool, float* __restrict__ out) {
    int i = blockIdx.x * blockDim.x + threadIdx.x;
    if (i >= POOL_N) return;
    int cell = i & (R2 - 1);
    int f    = (i >> 14) & 127;
    int kb   = i >> 21;
    float cnt = g_cnt[kb * R2 + cell];
    out[i] = pool[(size_t)(kb * R2 + cell) * 128 + f] / fmaxf(cnt, 1.0f);
}

// ---------------- host orchestration ----------------
extern "C" void kernel_launch(void* const* d_in, const int* in_sizes, int n_in,
                              void* d_out, int out_size) {
    const float* p        = (const float*)d_in[0];
    const float* fc_pos_W = (const float*)d_in[1];
    const float* fc_pos_b = (const float*)d_in[2];
    const float* bW0      = (const float*)d_in[3];
    const float* bb0      = (const float*)d_in[4];
    const float* bW1      = (const float*)d_in[5];
    const float* bb1      = (const float*)d_in[6];
    const float* bWs      = (const float*)d_in[7];
    const float* fc_c_W   = (const float*)d_in[8];
    const float* fc_c_b   = (const float*)d_in[9];
    float* out = (float*)d_out;

    float*    gnet = nullptr; cudaGetSymbolAddress((void**)&gnet, g_net);
    uint32_t* pA   = nullptr; cudaGetSymbolAddress((void**)&pA,   g_poolA);
    uint32_t* pB   = nullptr; cudaGetSymbolAddress((void**)&pB,   g_poolB);
    float*    pM   = nullptr; cudaGetSymbolAddress((void**)&pM,   g_mean);
    float*    gcnt = nullptr; cudaGetSymbolAddress((void**)&gcnt, g_cnt);
    __nv_bfloat16* wt = nullptr; cudaGetSymbolAddress((void**)&wt, g_wt);

    cudaFuncSetAttribute(k_block<1, true >, cudaFuncAttributeMaxDynamicSharedMemorySize, FSMEM);
    cudaFuncSetAttribute(k_block<2, true >, cudaFuncAttributeMaxDynamicSharedMemorySize, FSMEM);
    cudaFuncSetAttribute(k_block<2, false>, cudaFuncAttributeMaxDynamicSharedMemorySize, FSMEM);
    cudaFuncSetAttribute(k_fcc,             cudaFuncAttributeMaxDynamicSharedMemorySize, FC_SMEM);

    const int TPB = 256;
    const int GG  = BT / 128;   // 512

    k_reset<<<(3 * (POOL_N / 4) + TPB - 1) / TPB, TPB>>>();
    k_index<<<BT / TPB, TPB>>>(p);
    k_wsplit<<<(425984 + TPB - 1) / TPB, TPB>>>(bW0, bW1, bWs, fc_c_W);

    auto W0hi = [&](int b){ return wt + (size_t)b * 65536; };
    auto W0lo = [&](int b){ return wt + (size_t)b * 65536 + 32768; };
    auto W1hi = [&](int b){ return wt + 327680 + (size_t)b * 32768; };
    auto W1lo = [&](int b){ return wt + 327680 + (size_t)b * 32768 + 16384; };
    auto WShi = [&](int b){ return wt + 491520 + (size_t)b * 65536; };
    auto WSlo = [&](int b){ return wt + 491520 + (size_t)b * 65536 + 32768; };
    const __nv_bfloat16* FChi = wt + 819200;
    const __nv_bfloat16* FClo = wt + 819200 + 16384;

    k_block<1, true><<<GG, NT, FSMEM>>>(nullptr, p, fc_pos_W, fc_pos_b, nullptr, pA, 1u,
                                        W0hi(0), W0lo(0), W1hi(0), W1lo(0), WShi(0), WSlo(0),
                                        bb0, bb1, gnet);

    uint32_t* pin  = pA;
    uint32_t* pout = pB;
    for (int blk = 1; blk < 5; blk++) {
        uint32_t tag = (uint32_t)blk + 1;
        if (blk < 4) {
            k_block<2, true><<<GG, NT, FSMEM>>>(gnet, nullptr, nullptr, nullptr, pin, pout, tag,
                                                W0hi(blk), W0lo(blk), W1hi(blk), W1lo(blk),
                                                WShi(blk), WSlo(blk),
                                                bb0 + blk*128, bb1 + blk*128, gnet);
        } else {
            k_block<2, false><<<GG, NT, FSMEM>>>(gnet, nullptr, nullptr, nullptr, pin, nullptr, 0u,
                                                 W0hi(blk), W0lo(blk), W1hi(blk), W1lo(blk),
                                                 WShi(blk), WSlo(blk),
                                                 bb0 + blk*128, bb1 + blk*128, gnet);
        }
        uint32_t* tmp = pin; pin = pout; pout = tmp;
    }

    k_fcc<<<GG, NT, FC_SMEM>>>(gnet, pM, gcnt, FChi, FClo, fc_c_b);

    k_finalize<<<(POOL_N + TPB - 1) / TPB, TPB>>>(pM, out);
}

// round 17
// speedup vs baseline: 1.0175x; 1.0053x over previous
#include <cuda_runtime.h>
#include <cuda_bf16.h>
#include <cstdint>

// ---------------- problem constants ----------------
#define B       2
#define T       32768
#define BT      (B*T)           // 65536
#define R2      16384
#define POOL_N  (3*B*R2*128)
#define CNT_N   (3*B*R2)

// ---------------- scratch ----------------
__device__ float    g_net[BT*128];
__device__ uint32_t g_poolA[POOL_N];
__device__ uint32_t g_poolB[POOL_N];
__device__ float    g_mean[POOL_N];
__device__ float    g_cnt[CNT_N];
__device__ int      g_idx[3][BT];
__device__ __nv_bfloat16 g_wt[851968];

// ---------------- helpers ----------------
__device__ __forceinline__ uint32_t smem_u32(const void* p) {
    uint32_t a;
    asm("{ .reg .u64 t; cvta.to.shared.u64 t, %1; cvt.u32.u64 %0, t; }" : "=r"(a) : "l"(p));
    return a;
}
__device__ __forceinline__ void ldsm4(uint32_t& r0, uint32_t& r1, uint32_t& r2, uint32_t& r3,
                                      uint32_t a) {
    asm volatile("ldmatrix.sync.aligned.m8n8.x4.shared.b16 {%0,%1,%2,%3}, [%4];"
        : "=r"(r0), "=r"(r1), "=r"(r2), "=r"(r3) : "r"(a));
}
__device__ __forceinline__ void mma16816(float* c, const uint32_t* a, uint32_t b0, uint32_t b1) {
    asm("mma.sync.aligned.m16n8k16.row.col.f32.bf16.bf16.f32 "
        "{%0,%1,%2,%3}, {%4,%5,%6,%7}, {%8,%9}, {%0,%1,%2,%3};"
        : "+f"(c[0]), "+f"(c[1]), "+f"(c[2]), "+f"(c[3])
        : "r"(a[0]), "r"(a[1]), "r"(a[2]), "r"(a[3]), "r"(b0), "r"(b1));
}
__device__ __forceinline__ uint32_t b2u(__nv_bfloat162 v) {
    return *reinterpret_cast<uint32_t*>(&v);
}
__device__ __forceinline__ void cp16(uint32_t dst, const void* src) {
    asm volatile("cp.async.ca.shared.global [%0], [%1], 16;" :: "r"(dst), "l"(src));
}
__device__ __forceinline__ uint32_t sw(int r, int cb) {
    return (uint32_t)(r * 128 + ((((cb >> 4) ^ (r & 7)) & 7) << 4) + (cb & 15));
}
__device__ __forceinline__ uint32_t penc(float f, uint32_t tag) {
    uint32_t u = __float_as_uint(f);
    uint32_t e = (u >> 31) ? ~u : (u | 0x80000000u);
    return (tag << 29) | (e >> 3);
}
__device__ __forceinline__ float pdec(uint32_t w) {
    uint32_t e = (w & 0x1FFFFFFFu) << 3;
    return (e & 0x80000000u) ? __uint_as_float(e & 0x7FFFFFFFu)
                             : __uint_as_float(~e);
}
__device__ __forceinline__ void split2(float x, float y, uint32_t& hi, uint32_t& lo) {
    __nv_bfloat162 h, l;
    h.x = __float2bfloat16(x); h.y = __float2bfloat16(y);
    l.x = __float2bfloat16(x - __bfloat162float(h.x));
    l.y = __float2bfloat16(y - __bfloat162float(h.y));
    hi = b2u(h); lo = b2u(l);
}

// ---------------- single upfront reset ----------------
__global__ void k_reset() {
    int i = blockIdx.x * blockDim.x + threadIdx.x;
    const int Q = POOL_N / 4;
    uint4 z; z.x = z.y = z.z = z.w = 0u;
    if (i < Q)               ((uint4*)g_poolA)[i]      = z;
    else if (i < 2*Q)        ((uint4*)g_poolB)[i - Q]  = z;
    else if (i < 3*Q)        ((uint4*)g_mean)[i - 2*Q] = z;
    if (i < CNT_N) g_cnt[i] = 0.0f;
}

// ---------------- index computation ----------------
__global__ void k_index(const float* __restrict__ p) {
    int t = blockIdx.x * blockDim.x + threadIdx.x;
    if (t >= BT) return;
    float x = p[t*3+0], y = p[t*3+1], z = p[t*3+2];
    float cu[3] = {x, x, y};
    float cv[3] = {z, y, z};
    const float hi = (float)(1.0 - 1e-5);
    #pragma unroll
    for (int k = 0; k < 3; k++) {
        float u = cu[k] / 1.101f + 0.5f;
        float v = cv[k] / 1.101f + 0.5f;
        u = fminf(fmaxf(u, 0.0f), hi);
        v = fminf(fmaxf(v, 0.0f), hi);
        g_idx[k][t] = (int)(u * 128.0f) + 128 * (int)(v * 128.0f);
    }
}

// ---------------- weight pre-split ----------------
__global__ void k_wsplit(const float* __restrict__ W0, const float* __restrict__ W1,
                         const float* __restrict__ Ws, const float* __restrict__ fcW) {
    int i = blockIdx.x * blockDim.x + threadIdx.x;
    if (i >= 425984) return;
    const float* src; int K, base, e;
    if (i < 163840)       { int blk = i / 32768;            e = i % 32768; K = 256; src = W0 + blk*32768; base = blk*65536; }
    else if (i < 245760)  { int j = i - 163840; int blk = j / 16384; e = j % 16384; K = 128; src = W1 + blk*16384; base = 327680 + blk*32768; }
    else if (i < 409600)  { int j = i - 245760; int blk = j / 32768; e = j % 32768; K = 256; src = Ws + blk*32768; base = 491520 + blk*65536; }
    else                  { e = i - 409600; K = 128; src = fcW; base = 819200; }
    int n = e / K, k = e % K;
    float v = src[(size_t)k * 128 + n];
    __nv_bfloat16 hi = __float2bfloat16(v);
    __nv_bfloat16 lo = __float2bfloat16(v - __bfloat162float(hi));
    g_wt[base + (size_t)n * K + k]           = hi;
    g_wt[base + (size_t)128 * K + n * K + k] = lo;
}

// =====================================================================
// Single-A-pass fused block: W0 & Ws MMAs together, then W1.
// 256 threads, 8 warps (2M x 4N), warp tile m64 x n32.
// SMEM: bias 1KB | A planes 4x16KB (reluH,reluL,rawH,rawL; later hidden)
//       | B sets 2 x 4x16KB (W0h,W0l,Wsh,Wsl)
// =====================================================================
#define PLANE   16384
#define AOFF    1024u
#define SETB    (4*PLANE)
#define BOFF    (AOFF + 4*PLANE)
#define FSMEM   (int)(BOFF + 2*SETB)     // 197632
#define NTB     256

template<int ASRC, bool SCATTER>
__global__ __launch_bounds__(NTB, 1)
void k_block(const float* __restrict__ A1,
             const float* __restrict__ P,
             const float* __restrict__ fcW,
             const float* __restrict__ fcb,
             const uint32_t* __restrict__ poolIn,
             uint32_t* __restrict__ poolOut,
             uint32_t tag,
             const __nv_bfloat16* __restrict__ W0hi, const __nv_bfloat16* __restrict__ W0lo,
             const __nv_bfloat16* __restrict__ W1hi, const __nv_bfloat16* __restrict__ W1lo,
             const __nv_bfloat16* __restrict__ WShi, const __nv_bfloat16* __restrict__ WSlo,
             const float* __restrict__ b0, const float* __restrict__ b1,
             float* __restrict__ C) {
    extern __shared__ __align__(16) char smem[];
    float* b0S = (float*)smem;
    float* b1S = (float*)(smem + 512);
    const int tid  = threadIdx.x, lane = tid & 31, wid = tid >> 5;
    const int m0   = blockIdx.x * 128;
    const int wm   = (wid & 1) * 64;
    const int wn   = (wid >> 1) * 32;
    const uint32_t sb = smem_u32(smem);

    if (tid < 128) { b0S[tid] = b0[tid]; b1S[tid] = b1[tid]; }

    const int aRow  = wm + (lane & 15);
    const int aCoff = (lane >> 4) * 8;
    const int bRow  = wn + (lane & 7) + ((lane >> 4) << 3);
    const int bCoff = ((lane >> 3) & 1) * 8;

    float acc0[4][4][4] = {};   // W0 accumulators
    float acc1[4][4][4] = {};   // Ws accumulators

    auto loadA = [&](int ch, float4* vb) {
        const int K0 = ch * 64;
        #pragma unroll
        for (int j = 0; j < 8; j++) {
            int i = tid + j * NTB;
            int r = i >> 4, c4 = (i & 15) << 2;
            int m = m0 + r;
            if (ASRC == 1) {
                float p0 = P[m*3+0], p1 = P[m*3+1], p2 = P[m*3+2];
                int cg = K0 + c4;
                float4 v;
                v.x = fmaf(p0, fcW[cg+0], fmaf(p1, fcW[256+cg+0], fmaf(p2, fcW[512+cg+0], fcb[cg+0])));
                v.y = fmaf(p0, fcW[cg+1], fmaf(p1, fcW[256+cg+1], fmaf(p2, fcW[512+cg+1], fcb[cg+1])));
                v.z = fmaf(p0, fcW[cg+2], fmaf(p1, fcW[256+cg+2], fmaf(p2, fcW[512+cg+2], fcb[cg+2])));
                v.w = fmaf(p0, fcW[cg+3], fmaf(p1, fcW[256+cg+3], fmaf(p2, fcW[512+cg+3], fcb[cg+3])));
                vb[j] = v;
            } else if (K0 >= 128) {
                int b = m >> 15;
                int c0 = (K0 - 128) + c4;
                float4 s; s.x = s.y = s.z = s.w = 0.0f;
                #pragma unroll
                for (int k = 0; k < 3; k++) {
                    int cell = g_idx[k][m];
                    uint4 pv = *(const uint4*)&poolIn[((size_t)((k*B + b)*R2) + cell)*128 + c0];
                    s.x += pdec(pv.x); s.y += pdec(pv.y);
                    s.z += pdec(pv.z); s.w += pdec(pv.w);
                }
                vb[j] = s;
            } else {
                vb[j] = *(const float4*)&A1[(size_t)m * 128 + K0 + c4];
            }
        }
    };
    // dual split: raw -> planes 2/3, relu -> planes 0/1
    auto storeA2 = [&](const float4* vb) {
        #pragma unroll
        for (int j = 0; j < 8; j++) {
            int i = tid + j * NTB;
            int r = i >> 4, c4 = (i & 15) << 2;
            float4 v = vb[j];
            uint32_t off = sw(r, c4 * 2);
            uint32_t h0, l0, h1, l1;
            split2(v.x, v.y, h0, l0);
            split2(v.z, v.w, h1, l1);
            *(uint2*)(smem + AOFF + 2*PLANE + off) = make_uint2(h0, h1);
            *(uint2*)(smem + AOFF + 3*PLANE + off) = make_uint2(l0, l1);
            float rx = fmaxf(v.x, 0.f), ry = fmaxf(v.y, 0.f);
            float rz = fmaxf(v.z, 0.f), rw = fmaxf(v.w, 0.f);
            split2(rx, ry, h0, l0);
            split2(rz, rw, h1, l1);
            *(uint2*)(smem + AOFF + off)         = make_uint2(h0, h1);
            *(uint2*)(smem + AOFF + PLANE + off) = make_uint2(l0, l1);
        }
    };
    // both weight sets (W0 + Ws) for chunk ch into buffer set
    auto cpB2 = [&](int ch, int set) {
        const int K0 = ch * 64;
        const uint32_t base = sb + BOFF + (uint32_t)set * SETB;
        #pragma unroll
        for (int j = 0; j < 4; j++) {
            int i = tid + j * NTB;
            int r = i >> 3, c8 = (i & 7) << 3;
            uint32_t off = sw(r, c8 * 2);
            cp16(base + off,           &W0hi[(size_t)r * 256 + K0 + c8]);
            cp16(base + PLANE + off,   &W0lo[(size_t)r * 256 + K0 + c8]);
            cp16(base + 2*PLANE + off, &WShi[(size_t)r * 256 + K0 + c8]);
            cp16(base + 3*PLANE + off, &WSlo[(size_t)r * 256 + K0 + c8]);
        }
        asm volatile("cp.async.commit_group;" ::: "memory");
    };
    auto cpBW1 = [&](int ch, int set) {
        const int K0 = ch * 64;
        const uint32_t base = sb + BOFF + (uint32_t)set * SETB;
        #pragma unroll
        for (int j = 0; j < 4; j++) {
            int i = tid + j * NTB;
            int r = i >> 3, c8 = (i & 7) << 3;
            uint32_t off = sw(r, c8 * 2);
            cp16(base + off,         &W1hi[(size_t)r * 128 + K0 + c8]);
            cp16(base + PLANE + off, &W1lo[(size_t)r * 128 + K0 + c8]);
        }
        asm volatile("cp.async.commit_group;" ::: "memory");
    };
    // one GEMM over one 64-k chunk, m64 warp tile
    auto mmaOne = [&](float (&acc)[4][4][4], uint32_t aBase, uint32_t bBase) {
        #pragma unroll
        for (int ks = 0; ks < 64; ks += 16) {
            uint32_t ah[4][4], al[4][4];
            uint32_t c0 = (uint32_t)((ks + aCoff) * 2);
            #pragma unroll
            for (int mf = 0; mf < 4; mf++) {
                ldsm4(ah[mf][0], ah[mf][1], ah[mf][2], ah[mf][3],
                      sb + aBase + sw(aRow + mf*16, c0));
                ldsm4(al[mf][0], al[mf][1], al[mf][2], al[mf][3],
                      sb + aBase + PLANE + sw(aRow + mf*16, c0));
            }
            uint32_t bh[4][2], bl[4][2];
            #pragma unroll
            for (int nf2 = 0; nf2 < 2; nf2++) {
                uint32_t ad = sw(bRow + nf2*16, (uint32_t)((ks + bCoff) * 2));
                ldsm4(bh[nf2*2][0], bh[nf2*2][1], bh[nf2*2+1][0], bh[nf2*2+1][1], sb + bBase + ad);
                ldsm4(bl[nf2*2][0], bl[nf2*2][1], bl[nf2*2+1][0], bl[nf2*2+1][1], sb + bBase + PLANE + ad);
            }
            #pragma unroll
            for (int nf = 0; nf < 4; nf++)
                #pragma unroll
                for (int mf = 0; mf < 4; mf++)
                    mma16816(acc[mf][nf], ah[mf], bh[nf][0], bh[nf][1]);
            #pragma unroll
            for (int nf = 0; nf < 4; nf++)
                #pragma unroll
                for (int mf = 0; mf < 4; mf++)
                    mma16816(acc[mf][nf], ah[mf], bl[nf][0], bl[nf][1]);
            #pragma unroll
            for (int nf = 0; nf < 4; nf++)
                #pragma unroll
                for (int mf = 0; mf < 4; mf++)
                    mma16816(acc[mf][nf], al[mf], bh[nf][0], bh[nf][1]);
        }
    };

    // ================= W0 + Ws joint phase (K=256) =================
    float4 areg[8];
    loadA(0, areg);
    cpB2(0, 0);
    #pragma unroll
    for (int ch = 0; ch < 4; ch++) {
        const int set = ch & 1;
        __syncthreads();                 // prior MMAs done with A planes + set^1
        storeA2(areg);
        asm volatile("cp.async.wait_group 0;" ::: "memory");
        __syncthreads();                 // A planes + B(ch) visible
        if (ch < 3) {
            cpB2(ch + 1, set ^ 1);
            loadA(ch + 1, areg);
        } else {
            cpBW1(0, set ^ 1);           // W1 ch0 -> set0
        }
        mmaOne(acc0, AOFF,           BOFF + (uint32_t)set * SETB);
        mmaOne(acc1, AOFF + 2*PLANE, BOFF + (uint32_t)set * SETB + 2*PLANE);
    }
    __syncthreads();                     // last MMAs done (A planes free)

    // hidden = relu(acc0 + b0) -> A-plane space; acc0 = b1
    #pragma unroll
    for (int mf = 0; mf < 4; mf++) {
        int mloc = wm + mf*16 + (lane >> 2);
        #pragma unroll
        for (int nf = 0; nf < 4; nf++) {
            int n = wn + nf*8 + (lane & 3) * 2;
            uint32_t hb = AOFF + (uint32_t)(n >> 6) * 2 * PLANE;
            #pragma unroll
            for (int q = 0; q < 2; q++) {
                int r = mloc + q * 8;
                float h0 = fmaxf(acc0[mf][nf][2*q]   + b0S[n],   0.0f);
                float h1 = fmaxf(acc0[mf][nf][2*q+1] + b0S[n+1], 0.0f);
                uint32_t hh, ll;
                split2(h0, h1, hh, ll);
                uint32_t off = sw(r, (n & 63) * 2);
                *(uint32_t*)(smem + hb + off)         = hh;
                *(uint32_t*)(smem + hb + PLANE + off) = ll;
            }
            #pragma unroll
            for (int q = 0; q < 4; q++) acc0[mf][nf][q] = b1S[n + (q & 1)];
        }
    }
    cpBW1(1, 1);                         // W1 ch1 -> set1
    asm volatile("cp.async.wait_group 0;" ::: "memory");
    __syncthreads();                     // hidden + W1 B visible

    // ================= W1 (K=128, A = hidden planes) =================
    mmaOne(acc0, AOFF,           BOFF);
    mmaOne(acc0, AOFF + 2*PLANE, BOFF + SETB);

    // ---- epilogue: net = acc1 + acc0(dx+b1); write + tagged scatter-max
    #pragma unroll
    for (int mf = 0; mf < 4; mf++) {
        const int m  = m0 + wm + mf*16 + (lane >> 2);
        const int bb = m >> 15;
        int cellA[3], cellB[3];
        if (SCATTER) {
            #pragma unroll
            for (int k = 0; k < 3; k++) {
                cellA[k] = g_idx[k][m];
                cellB[k] = g_idx[k][m + 8];
            }
        }
        #pragma unroll
        for (int nf = 0; nf < 4; nf++) {
            int n = wn + nf*8 + (lane & 3) * 2;
            float2 v0, v1;
            v0.x = acc1[mf][nf][0] + acc0[mf][nf][0];
            v0.y = acc1[mf][nf][1] + acc0[mf][nf][1];
            v1.x = acc1[mf][nf][2] + acc0[mf][nf][2];
            v1.y = acc1[mf][nf][3] + acc0[mf][nf][3];
            *(float2*)&C[(size_t)m * 128 + n]     = v0;
            *(float2*)&C[(size_t)(m+8) * 128 + n] = v1;
            if (SCATTER) {
                uint32_t e00 = penc(v0.x, tag), e01 = penc(v0.y, tag);
                uint32_t e10 = penc(v1.x, tag), e11 = penc(v1.y, tag);
                #pragma unroll
                for (int k = 0; k < 3; k++) {
                    uint32_t* pA = &poolOut[((size_t)((k*B + bb)*R2) + cellA[k])*128 + n];
                    uint32_t* pB = &poolOut[((size_t)((k*B + bb)*R2) + cellB[k])*128 + n];
                    atomicMax(pA,     e00); atomicMax(pA + 1, e01);
                    atomicMax(pB,     e10); atomicMax(pB + 1, e11);
                }
            }
        }
    }
}

// =====================================================================
// fc_c GEMM (K=128) with fused scatter-sum, 512 threads (unchanged R16)
// =====================================================================
#define SOFF    1024u
#define SETSZ   (4*PLANE)
#define FC_SMEM (int)(1024 + 2 * 4 * PLANE)
#define NTF     512

#define MMA_TERMS(acc, ah0, ah1, al0, al1, bh, bl)            \
    do {                                                      \
        _Pragma("unroll")                                     \
        for (int nf = 0; nf < 4; nf++) {                      \
            mma16816(acc[0][nf], ah0, bh[nf][0], bh[nf][1]);  \
            mma16816(acc[1][nf], ah1, bh[nf][0], bh[nf][1]);  \
        }                                                     \
        _Pragma("unroll")                                     \
        for (int nf = 0; nf < 4; nf++) {                      \
            mma16816(acc[0][nf], ah0, bl[nf][0], bl[nf][1]);  \
            mma16816(acc[1][nf], ah1, bl[nf][0], bl[nf][1]);  \
        }                                                     \
        _Pragma("unroll")                                     \
        for (int nf = 0; nf < 4; nf++) {                      \
            mma16816(acc[0][nf], al0, bh[nf][0], bh[nf][1]);  \
            mma16816(acc[1][nf], al1, bh[nf][0], bh[nf][1]);  \
        }                                                     \
    } while (0)

__global__ __launch_bounds__(NTF, 1)
void k_fcc(const float* __restrict__ A1,
           float* __restrict__ poolOut, float* __restrict__ cnt,
           const __nv_bfloat16* __restrict__ Whi, const __nv_bfloat16* __restrict__ Wlo,
           const float* __restrict__ bias) {
    extern __shared__ __align__(16) char smem[];
    float* biasS = (float*)smem;
    const int tid  = threadIdx.x, lane = tid & 31, wid = tid >> 5;
    const int m0   = blockIdx.x * 128;
    const int wm   = (wid & 3) * 32;
    const int wn   = (wid >> 2) * 32;
    const uint32_t sb = smem_u32(smem);

    if (tid < 128) biasS[tid] = bias[tid];

    const int aRow  = wm + (lane & 15);
    const int aCoff = (lane >> 4) * 8;
    const int bRow  = wn + (lane & 7) + ((lane >> 4) << 3);
    const int bCoff = ((lane >> 3) & 1) * 8;

    float acc[2][4][4] = {};

    auto loadA = [&](int ch, float4* vb) {
        #pragma unroll
        for (int j = 0; j < 4; j++) {
            int i = tid + j * NTF;
            int r = i >> 4, c4 = (i & 15) << 2;
            vb[j] = *(const float4*)&A1[(size_t)(m0 + r) * 128 + ch * 64 + c4];
        }
    };
    auto storeA = [&](int set, const float4* vb) {
        const uint32_t base = SOFF + (uint32_t)set * SETSZ;
        #pragma unroll
        for (int j = 0; j < 4; j++) {
            int i = tid + j * NTF;
            int r = i >> 4, c4 = (i & 15) << 2;
            float4 v = vb[j];
            uint32_t h0, l0, h1, l1;
            split2(v.x, v.y, h0, l0);
            split2(v.z, v.w, h1, l1);
            uint32_t off = sw(r, c4 * 2);
            *(uint2*)(smem + base + off)         = make_uint2(h0, h1);
            *(uint2*)(smem + base + PLANE + off) = make_uint2(l0, l1);
        }
    };
    auto cpB = [&](int ch, int set) {
        const uint32_t base = sb + SOFF + (uint32_t)set * SETSZ + 2 * PLANE;
        #pragma unroll
        for (int j = 0; j < 2; j++) {
            int i = tid + j * NTF;
            int r = i >> 3, c8 = (i & 7) << 3;
            uint32_t off = sw(r, c8 * 2);
            cp16(base + off,         &Whi[(size_t)r * 128 + ch * 64 + c8]);
            cp16(base + PLANE + off, &Wlo[(size_t)r * 128 + ch * 64 + c8]);
        }
        asm volatile("cp.async.commit_group;" ::: "memory");
    };
    auto mmaChunk = [&](uint32_t aBase, uint32_t bBase) {
        #pragma unroll
        for (int ks = 0; ks < 64; ks += 16) {
            uint32_t ah0[4], ah1[4], al0[4], al1[4];
            uint32_t c0 = (uint32_t)((ks + aCoff) * 2);
            ldsm4(ah0[0], ah0[1], ah0[2], ah0[3], sb + aBase + sw(aRow,      c0));
            ldsm4(ah1[0], ah1[1], ah1[2], ah1[3], sb + aBase + sw(aRow + 16, c0));
            ldsm4(al0[0], al0[1], al0[2], al0[3], sb + aBase + PLANE + sw(aRow,      c0));
            ldsm4(al1[0], al1[1], al1[2], al1[3], sb + aBase + PLANE + sw(aRow + 16, c0));
            uint32_t bh[4][2], bl[4][2];
            #pragma unroll
            for (int nf2 = 0; nf2 < 2; nf2++) {
                uint32_t ad = sw(bRow + nf2*16, (uint32_t)((ks + bCoff) * 2));
                ldsm4(bh[nf2*2][0], bh[nf2*2][1], bh[nf2*2+1][0], bh[nf2*2+1][1], sb + bBase + ad);
                ldsm4(bl[nf2*2][0], bl[nf2*2][1], bl[nf2*2+1][0], bl[nf2*2+1][1], sb + bBase + PLANE + ad);
            }
            MMA_TERMS(acc, ah0, ah1, al0, al1, bh, bl);
        }
    };

    float4 areg[4];
    loadA(0, areg);
    cpB(0, 0);
    storeA(0, areg);
    asm volatile("cp.async.wait_group 0;" ::: "memory");
    #pragma unroll
    for (int ch = 0; ch < 2; ch++) {
        const int set = ch & 1;
        __syncthreads();
        if (ch < 1) { cpB(1, 1); loadA(1, areg); }
        mmaChunk(SOFF + (uint32_t)set * SETSZ, SOFF + (uint32_t)set * SETSZ + 2*PLANE);
        if (ch < 1) storeA(1, areg);
        asm volatile("cp.async.wait_group 0;" ::: "memory");
    }

    #pragma unroll
    for (int mf = 0; mf < 2; mf++) {
        const int m  = m0 + wm + mf*16 + (lane >> 2);
        const int bb = m >> 15;
        int cellA[3], cellB[3];
        #pragma unroll
        for (int k = 0; k < 3; k++) {
            cellA[k] = g_idx[k][m];
            cellB[k] = g_idx[k][m + 8];
        }
        #pragma unroll
        for (int nf = 0; nf < 4; nf++) {
            int n = wn + nf*8 + (lane & 3) * 2;
            float2 v0, v1;
            v0.x = acc[mf][nf][0] + biasS[n];
            v0.y = acc[mf][nf][1] + biasS[n+1];
            v1.x = acc[mf][nf][2] + biasS[n];
            v1.y = acc[mf][nf][3] + biasS[n+1];
            #pragma unroll
            for (int k = 0; k < 3; k++) {
                float* pA = &poolOut[((size_t)((k*B + bb)*R2) + cellA[k])*128 + n];
                float* pB = &poolOut[((size_t)((k*B + bb)*R2) + cellB[k])*128 + n];
                atomicAdd(pA,     v0.x); atomicAdd(pA + 1, v0.y);
                atomicAdd(pB,     v1.x); atomicAdd(pB + 1, v1.y);
                if (n == 0) {
                    atomicAdd(&cnt[(k*B + bb)*R2 + cellA[k]], 1.0f);
                    atomicAdd(&cnt[(k*B + bb)*R2 + cellB[k]], 1.0f);
                }
            }
        }
    }
}

// ---------------- finalize ----------------
__global__ void k_finalize(const float* __restrict__ pool, float* __restrict__ out) {
    int i = blockIdx.x * blockDim.x + threadIdx.x;
    if (i >= POOL_N) return;
    int cell = i & (R2 - 1);
    int f    = (i >> 14) & 127;
    int kb   = i >> 21;
    float cnt = g_cnt[kb * R2 + cell];
    out[i] = pool[(size_t)(kb * R2 + cell) * 128 + f] / fmaxf(cnt, 1.0f);
}

// ---------------- host orchestration ----------------
extern "C" void kernel_launch(void* const* d_in, const int* in_sizes, int n_in,
                              void* d_out, int out_size) {
    const float* p        = (const float*)d_in[0];
    const float* fc_pos_W = (const float*)d_in[1];
    const float* fc_pos_b = (const float*)d_in[2];
    const float* bW0      = (const float*)d_in[3];
    const float* bb0      = (const float*)d_in[4];
    const float* bW1      = (const float*)d_in[5];
    const float* bb1      = (const float*)d_in[6];
    const float* bWs      = (const float*)d_in[7];
    const float* fc_c_W   = (const float*)d_in[8];
    const float* fc_c_b   = (const float*)d_in[9];
    float* out = (float*)d_out;

    float*    gnet = nullptr; cudaGetSymbolAddress((void**)&gnet, g_net);
    uint32_t* pA   = nullptr; cudaGetSymbolAddress((void**)&pA,   g_poolA);
    uint32_t* pB   = nullptr; cudaGetSymbolAddress((void**)&pB,   g_poolB);
    float*    pM   = nullptr; cudaGetSymbolAddress((void**)&pM,   g_mean);
    float*    gcnt = nullptr; cudaGetSymbolAddress((void**)&gcnt, g_cnt);
    __nv_bfloat16* wt = nullptr; cudaGetSymbolAddress((void**)&wt, g_wt);

    cudaFuncSetAttribute(k_block<1, true >, cudaFuncAttributeMaxDynamicSharedMemorySize, FSMEM);
    cudaFuncSetAttribute(k_block<2, true >, cudaFuncAttributeMaxDynamicSharedMemorySize, FSMEM);
    cudaFuncSetAttribute(k_block<2, false>, cudaFuncAttributeMaxDynamicSharedMemorySize, FSMEM);
    cudaFuncSetAttribute(k_fcc,             cudaFuncAttributeMaxDynamicSharedMemorySize, FC_SMEM);

    const int TPB = 256;
    const int GG  = BT / 128;   // 512

    k_reset<<<(3 * (POOL_N / 4) + TPB - 1) / TPB, TPB>>>();
    k_index<<<BT / TPB, TPB>>>(p);
    k_wsplit<<<(425984 + TPB - 1) / TPB, TPB>>>(bW0, bW1, bWs, fc_c_W);

    auto W0hi = [&](int b){ return wt + (size_t)b * 65536; };
    auto W0lo = [&](int b){ return wt + (size_t)b * 65536 + 32768; };
    auto W1hi = [&](int b){ return wt + 327680 + (size_t)b * 32768; };
    auto W1lo = [&](int b){ return wt + 327680 + (size_t)b * 32768 + 16384; };
    auto WShi = [&](int b){ return wt + 491520 + (size_t)b * 65536; };
    auto WSlo = [&](int b){ return wt + 491520 + (size_t)b * 65536 + 32768; };
    const __nv_bfloat16* FChi = wt + 819200;
    const __nv_bfloat16* FClo = wt + 819200 + 16384;

    k_block<1, true><<<GG, NTB, FSMEM>>>(nullptr, p, fc_pos_W, fc_pos_b, nullptr, pA, 1u,
                                         W0hi(0), W0lo(0), W1hi(0), W1lo(0), WShi(0), WSlo(0),
                                         bb0, bb1, gnet);

    uint32_t* pin  = pA;
    uint32_t* pout = pB;
    for (int blk = 1; blk < 5; blk++) {
        uint32_t tag = (uint32_t)blk + 1;
        if (blk < 4) {
            k_block<2, true><<<GG, NTB, FSMEM>>>(gnet, nullptr, nullptr, nullptr, pin, pout, tag,
                                                 W0hi(blk), W0lo(blk), W1hi(blk), W1lo(blk),
                                                 WShi(blk), WSlo(blk),
                                                 bb0 + blk*128, bb1 + blk*128, gnet);
        } else {
            k_block<2, false><<<GG, NTB, FSMEM>>>(gnet, nullptr, nullptr, nullptr, pin, nullptr, 0u,
                                                  W0hi(blk), W0lo(blk), W1hi(blk), W1lo(blk),
                                                  WShi(blk), WSlo(blk),
                                                  bb0 + blk*128, bb1 + blk*128, gnet);
        }
        uint32_t* tmp = pin; pin = pout; pout = tmp;
    }

    k_fcc<<<GG, NTF, FC_SMEM>>>(gnet, pM, gcnt, FChi, FClo, fc_c_b);

    k_finalize<<<(POOL_N + TPB - 1) / TPB, TPB>>>(pM, out);
}